// round 1
// baseline (speedup 1.0000x reference)
#include <cuda_runtime.h>
#include <cstdint>
#include <cstdio>

// ---------------- fixed problem shape ----------------
#define B_   64
#define D_   512
#define L0_  512
#define L1_  256
#define WS_  128
#define H0_  128
#define H1_  64
#define N0_  (L0_ + WS_)   // 640
#define N1_  (L1_ + WS_)   // 384

// ---------------- device scratch (no allocs allowed) ----------------
__device__ float  g_nrm0[(size_t)B_ * N0_ * D_];   // normalized nodes, scale 0 (~84MB)
__device__ float  g_nrm1[(size_t)B_ * N1_ * D_];   // (~50MB)
__device__ int    g_eidx0[N0_], g_eidx1[N1_];      // selected hyperedge per node (-1 = none)
__device__ int    g_cnt0[N0_],  g_cnt1[N1_];       // positive count per node
__device__ int    g_nvalid[2];
__device__ double g_loss[2];

template<int S> __device__ __forceinline__ float* nrmP()  { return S ? g_nrm1  : g_nrm0;  }
template<int S> __device__ __forceinline__ int*   eidxP() { return S ? g_eidx1 : g_eidx0; }
template<int S> __device__ __forceinline__ int*   cntP()  { return S ? g_cnt1  : g_cnt0;  }

// ---------------- init: zero loss accumulators (graph replays!) ----------------
__global__ void init_kernel() {
    g_loss[0] = 0.0; g_loss[1] = 0.0;
}

// ---------------- adjacency: adj_bin = softmax(relu(3 * enod@ehy^T)) > 0.5 ----------------
// One block per node n. 128 threads; thread h computes dot(enod[n], ehy[h]).
template<int S>
__global__ void __launch_bounds__(128)
adj_kernel(const float* __restrict__ enod, const float* __restrict__ ehy,
           float* __restrict__ adj_out, int H)
{
    const int n   = blockIdx.x;
    const int tid = threadIdx.x;

    __shared__ float xrow[D_];
    __shared__ float et[128][33];    // padded, conflict-free compute reads
    __shared__ float rbuf[128];
    __shared__ int   widx;

    *(float4*)&xrow[tid * 4] = *(const float4*)(enod + (size_t)n * D_ + tid * 4);

    float acc = 0.f;
    const int nf4 = H * 8;           // float4s per 32-wide k tile
    for (int kk = 0; kk < D_; kk += 32) {
        __syncthreads();
        for (int f = tid; f < nf4; f += 128) {
            int h = f >> 3, c4 = f & 7;
            float4 v = *(const float4*)(ehy + (size_t)h * D_ + kk + c4 * 4);
            et[h][c4 * 4 + 0] = v.x; et[h][c4 * 4 + 1] = v.y;
            et[h][c4 * 4 + 2] = v.z; et[h][c4 * 4 + 3] = v.w;
        }
        __syncthreads();
        if (tid < H) {
            #pragma unroll
            for (int c = 0; c < 32; c++) acc += xrow[kk + c] * et[tid][c];
        }
    }

    // softmax over H lanes; entry > 0.5 is unique (softmax sums to 1) and is the max,
    // hence always inside top-k (k>=1): adj_bin = (p > 0.5), no top-k machinery.
    float z = (tid < H) ? fmaxf(3.0f * acc, 0.0f) : -1e30f;
    rbuf[tid] = z; __syncthreads();
    for (int o = 64; o > 0; o >>= 1) { if (tid < o) rbuf[tid] = fmaxf(rbuf[tid], rbuf[tid + o]); __syncthreads(); }
    float zmax = rbuf[0]; __syncthreads();
    float e = (tid < H) ? __expf(z - zmax) : 0.f;
    rbuf[tid] = e; __syncthreads();
    for (int o = 64; o > 0; o >>= 1) { if (tid < o) rbuf[tid] += rbuf[tid + o]; __syncthreads(); }
    float ssum = rbuf[0];
    if (tid == 0) widx = -1;
    __syncthreads();
    if (tid < H) {
        int bin = (e / ssum) > 0.5f;
        adj_out[(size_t)n * H + tid] = (float)bin;
        if (bin) widx = tid;    // at most one writer
    }
    __syncthreads();
    if (tid == 0) eidxP<S>()[n] = widx;
}

// ---------------- counts: cnt[n] = #{m != n : e[m]==e[n]}, nvalid = #{cnt>0} ----------------
template<int S>
__global__ void cnt_kernel(int N, int H)
{
    __shared__ int hist[128];
    __shared__ int vcount;
    const int tid = threadIdx.x;
    if (tid < H) hist[tid] = 0;
    if (tid == 0) vcount = 0;
    __syncthreads();
    for (int n = tid; n < N; n += blockDim.x) {
        int e = eidxP<S>()[n];
        if (e >= 0) atomicAdd(&hist[e], 1);
    }
    __syncthreads();
    int local = 0;
    for (int n = tid; n < N; n += blockDim.x) {
        int e = eidxP<S>()[n];
        int c = (e >= 0) ? hist[e] - 1 : 0;
        cntP<S>()[n] = c;
        if (c > 0) local++;
    }
    atomicAdd(&vcount, local);
    __syncthreads();
    if (tid == 0) g_nvalid[S] = vcount;
}

// ---------------- normalize: nrm[b,n,:] = row / max(||row||,1e-12) ----------------
template<int S>
__global__ void __launch_bounds__(128)
norm_kernel(const float* __restrict__ x, const float* __restrict__ w, int L, int N)
{
    const int n = blockIdx.x, b = blockIdx.y, tid = threadIdx.x;
    const float* src = (n < L) ? (x + ((size_t)b * L + n) * D_)
                               : (w + (size_t)(n - L) * D_);
    float4 v = *(const float4*)(src + tid * 4);
    float ss = v.x*v.x + v.y*v.y + v.z*v.z + v.w*v.w;
    #pragma unroll
    for (int o = 16; o > 0; o >>= 1) ss += __shfl_down_sync(0xffffffffu, ss, o);
    __shared__ float sp[4];
    __shared__ float invs;
    if ((tid & 31) == 0) sp[tid >> 5] = ss;
    __syncthreads();
    if (tid == 0) {
        float t = sp[0] + sp[1] + sp[2] + sp[3];
        invs = 1.0f / fmaxf(sqrtf(t), 1e-12f);
    }
    __syncthreads();
    float iv = invs;
    float4 o4 = make_float4(v.x*iv, v.y*iv, v.z*iv, v.w*iv);
    *(float4*)(nrmP<S>() + ((size_t)b * N + n) * D_ + tid * 4) = o4;
}

// ---------------- fused sim GEMM + logsumexp + positive-sum ----------------
// grid = (N/64, B), 256 threads. 64x64 tile, 4x4 per thread, K=512 in steps of 16.
// Normalized rows => sim diag == 10 == max; fixed shift, no online max needed.
#define TM 64
#define TN 64
#define TK 16

template<int S>
__global__ void __launch_bounds__(256, 2)
sim_kernel(int N)
{
    __shared__ float As[TK][TM];
    __shared__ float Bs[TK][TN];
    __shared__ float rsum[TM];
    __shared__ float rpos[TM];
    __shared__ int   erow[TM];
    __shared__ int   ecol[TN];
    __shared__ float part2[8];

    const int tid = threadIdx.x;
    const int tx = tid & 15, ty = tid >> 4;
    const int rb = blockIdx.x * TM;
    const int b  = blockIdx.y;
    const float* base = nrmP<S>() + (size_t)b * N * D_;
    const int* eidx = eidxP<S>();
    const int* cnt  = cntP<S>();

    if (tid < TM) { rsum[tid] = 0.f; rpos[tid] = 0.f; erow[tid] = eidx[rb + tid]; }

    const int lr = tid >> 2;   // row within tile for loads
    const int lq = tid & 3;    // float4 quad within 16-wide k tile
    const float* Aptr = base + (size_t)(rb + lr) * D_ + lq * 4;

    const int nTiles = N / TN;
    for (int mt = 0; mt < nTiles; ++mt) {
        __syncthreads();                    // protect ecol / smem reuse across tiles
        if (tid < TN) ecol[tid] = eidx[mt * TN + tid];

        float acc[4][4];
        #pragma unroll
        for (int i = 0; i < 4; i++)
            #pragma unroll
            for (int j = 0; j < 4; j++) acc[i][j] = 0.f;

        const float* Bptr = base + (size_t)(mt * TN + lr) * D_ + lq * 4;

        for (int kk = 0; kk < D_; kk += TK) {
            float4 av = *(const float4*)(Aptr + kk);
            float4 bv = *(const float4*)(Bptr + kk);
            __syncthreads();
            As[lq*4+0][lr] = av.x; As[lq*4+1][lr] = av.y;
            As[lq*4+2][lr] = av.z; As[lq*4+3][lr] = av.w;
            Bs[lq*4+0][lr] = bv.x; Bs[lq*4+1][lr] = bv.y;
            Bs[lq*4+2][lr] = bv.z; Bs[lq*4+3][lr] = bv.w;
            __syncthreads();
            #pragma unroll
            for (int k = 0; k < TK; k++) {
                float4 a4 = *(const float4*)&As[k][ty * 4];
                float4 b4 = *(const float4*)&Bs[k][tx * 4];
                float ar[4] = {a4.x, a4.y, a4.z, a4.w};
                float br[4] = {b4.x, b4.y, b4.z, b4.w};
                #pragma unroll
                for (int i = 0; i < 4; i++)
                    #pragma unroll
                    for (int j = 0; j < 4; j++)
                        acc[i][j] = fmaf(ar[i], br[j], acc[i][j]);
            }
        }

        // epilogue for this 64x64 tile
        #pragma unroll
        for (int i = 0; i < 4; i++) {
            int row = ty * 4 + i;
            int rn  = rb + row;
            int en  = erow[row];
            float se = 0.f, pl = 0.f;
            #pragma unroll
            for (int j = 0; j < 4; j++) {
                float s = acc[i][j] * 10.0f;          // / tau
                se += __expf(s - 10.0f);              // shift by known max (diag)
                int mcol = tx * 4 + j;
                int m = mt * TN + mcol;
                if (en >= 0 && ecol[mcol] == en && m != rn) pl += s;
            }
            #pragma unroll
            for (int o = 8; o > 0; o >>= 1) {
                se += __shfl_down_sync(0xffffffffu, se, o, 16);
                pl += __shfl_down_sync(0xffffffffu, pl, o, 16);
            }
            if (tx == 0) { rsum[row] += se; rpos[row] += pl; }
        }
    }

    __syncthreads();
    float contrib = 0.f;
    if (tid < TM) {
        int c = cnt[rb + tid];
        if (c > 0) {
            float lse = 10.0f + logf(rsum[tid]);
            contrib = lse - rpos[tid] / (float)c;
        }
    }
    float v = contrib;
    #pragma unroll
    for (int o = 16; o > 0; o >>= 1) v += __shfl_down_sync(0xffffffffu, v, o);
    if ((tid & 31) == 0) part2[tid >> 5] = v;
    __syncthreads();
    if (tid == 0) atomicAdd(&g_loss[S], (double)(part2[0] + part2[1]));
}

// ---------------- finalize: loss = sum_s loss_s / (B * nvalid_s) ----------------
__global__ void final_kernel(float* out_loss)
{
    double l = 0.0;
    #pragma unroll
    for (int s = 0; s < 2; s++) {
        int nv = g_nvalid[s];
        if (nv > 0) l += g_loss[s] / (double)(B_ * nv);
    }
    *out_loss = (float)l;
}

// ---------------- launch ----------------
extern "C" void kernel_launch(void* const* d_in, const int* in_sizes, int n_in,
                              void* d_out, int out_size)
{
    const float* x0   = (const float*)d_in[0];
    const float* x1   = (const float*)d_in[1];
    const float* w0   = (const float*)d_in[2];
    const float* w1   = (const float*)d_in[3];
    const float* hy0  = (const float*)d_in[4];
    const float* hy1  = (const float*)d_in[5];
    const float* nod0 = (const float*)d_in[6];
    const float* nod1 = (const float*)d_in[7];
    float* out = (float*)d_out;

    float* adj0  = out;
    float* adj1  = out + (size_t)N0_ * H0_;
    float* lossp = out + (size_t)N0_ * H0_ + (size_t)N1_ * H1_;

    init_kernel<<<1, 1>>>();

    // scale 0
    adj_kernel<0><<<N0_, 128>>>(nod0, hy0, adj0, H0_);
    cnt_kernel<0><<<1, 256>>>(N0_, H0_);
    norm_kernel<0><<<dim3(N0_, B_), 128>>>(x0, w0, L0_, N0_);
    sim_kernel<0><<<dim3(N0_ / TM, B_), 256>>>(N0_);

    // scale 1
    adj_kernel<1><<<N1_, 128>>>(nod1, hy1, adj1, H1_);
    cnt_kernel<1><<<1, 256>>>(N1_, H1_);
    norm_kernel<1><<<dim3(N1_, B_), 128>>>(x1, w1, L1_, N1_);
    sim_kernel<1><<<dim3(N1_ / TM, B_), 256>>>(N1_);

    final_kernel<<<1, 1>>>(lossp);
}

// round 2
// speedup vs baseline: 4.7237x; 4.7237x over previous
#include <cuda_runtime.h>
#include <cuda_bf16.h>
#include <cstdint>

// ---------------- fixed problem shape ----------------
#define B_   64
#define D_   512
#define L0_  512
#define L1_  256
#define WS_  128
#define H0_  128
#define H1_  64
#define N0_  (L0_ + WS_)   // 640
#define N1_  (L1_ + WS_)   // 384

// ---------------- device scratch (no allocs allowed) ----------------
__device__ __nv_bfloat16 g_nb0[(size_t)B_ * N0_ * D_];   // normalized nodes bf16 (~42MB)
__device__ __nv_bfloat16 g_nb1[(size_t)B_ * N1_ * D_];   // (~25MB)
__device__ int    g_eidx0[N0_], g_eidx1[N1_];
__device__ int    g_cnt0[N0_],  g_cnt1[N1_];
__device__ int    g_nvalid[2];
__device__ double g_loss[2];

template<int S> __device__ __forceinline__ __nv_bfloat16* nbP() { return S ? g_nb1 : g_nb0; }
template<int S> __device__ __forceinline__ int* eidxP() { return S ? g_eidx1 : g_eidx0; }
template<int S> __device__ __forceinline__ int* cntP()  { return S ? g_cnt1  : g_cnt0;  }

// ---------------- init: zero loss accumulators (graph replays!) ----------------
__global__ void init_kernel() { g_loss[0] = 0.0; g_loss[1] = 0.0; }

// ---------------- adjacency: adj_bin = softmax(relu(3 * enod@ehy^T)) > 0.5 ----------------
// softmax row sums to 1 => at most one entry > 0.5 and it is the row max =>
// always inside top-k: adj_bin = (p > 0.5). No top-k machinery needed.
template<int S>
__global__ void __launch_bounds__(128)
adj_kernel(const float* __restrict__ enod, const float* __restrict__ ehy,
           float* __restrict__ adj_out, int H)
{
    const int n   = blockIdx.x;
    const int tid = threadIdx.x;

    __shared__ float xrow[D_];
    __shared__ float et[128][33];
    __shared__ float rbuf[128];
    __shared__ int   widx;

    *(float4*)&xrow[tid * 4] = *(const float4*)(enod + (size_t)n * D_ + tid * 4);

    float acc = 0.f;
    const int nf4 = H * 8;
    for (int kk = 0; kk < D_; kk += 32) {
        __syncthreads();
        for (int f = tid; f < nf4; f += 128) {
            int h = f >> 3, c4 = f & 7;
            float4 v = *(const float4*)(ehy + (size_t)h * D_ + kk + c4 * 4);
            et[h][c4 * 4 + 0] = v.x; et[h][c4 * 4 + 1] = v.y;
            et[h][c4 * 4 + 2] = v.z; et[h][c4 * 4 + 3] = v.w;
        }
        __syncthreads();
        if (tid < H) {
            #pragma unroll
            for (int c = 0; c < 32; c++) acc += xrow[kk + c] * et[tid][c];
        }
    }

    float z = (tid < H) ? fmaxf(3.0f * acc, 0.0f) : -1e30f;
    rbuf[tid] = z; __syncthreads();
    for (int o = 64; o > 0; o >>= 1) { if (tid < o) rbuf[tid] = fmaxf(rbuf[tid], rbuf[tid + o]); __syncthreads(); }
    float zmax = rbuf[0]; __syncthreads();
    float e = (tid < H) ? __expf(z - zmax) : 0.f;
    rbuf[tid] = e; __syncthreads();
    for (int o = 64; o > 0; o >>= 1) { if (tid < o) rbuf[tid] += rbuf[tid + o]; __syncthreads(); }
    float ssum = rbuf[0];
    if (tid == 0) widx = -1;
    __syncthreads();
    if (tid < H) {
        int bin = (e / ssum) > 0.5f;
        adj_out[(size_t)n * H + tid] = (float)bin;
        if (bin) widx = tid;
    }
    __syncthreads();
    if (tid == 0) eidxP<S>()[n] = widx;
}

// ---------------- counts: cnt[n] = #{m != n : e[m]==e[n]}, nvalid = #{cnt>0} ----------------
template<int S>
__global__ void cnt_kernel(int N, int H)
{
    __shared__ int hist[128];
    __shared__ int vcount;
    const int tid = threadIdx.x;
    if (tid < H) hist[tid] = 0;
    if (tid == 0) vcount = 0;
    __syncthreads();
    for (int n = tid; n < N; n += blockDim.x) {
        int e = eidxP<S>()[n];
        if (e >= 0) atomicAdd(&hist[e], 1);
    }
    __syncthreads();
    int local = 0;
    for (int n = tid; n < N; n += blockDim.x) {
        int e = eidxP<S>()[n];
        int c = (e >= 0) ? hist[e] - 1 : 0;
        cntP<S>()[n] = c;
        if (c > 0) local++;
    }
    atomicAdd(&vcount, local);
    __syncthreads();
    if (tid == 0) g_nvalid[S] = vcount;
}

// ---------------- normalize -> bf16: nb[b,n,:] = bf16(row / max(||row||,1e-12)) ----------------
template<int S>
__global__ void __launch_bounds__(128)
norm_kernel(const float* __restrict__ x, const float* __restrict__ w, int L, int N)
{
    const int n = blockIdx.x, b = blockIdx.y, tid = threadIdx.x;
    const float* src = (n < L) ? (x + ((size_t)b * L + n) * D_)
                               : (w + (size_t)(n - L) * D_);
    float4 v = *(const float4*)(src + tid * 4);
    float ss = v.x*v.x + v.y*v.y + v.z*v.z + v.w*v.w;
    #pragma unroll
    for (int o = 16; o > 0; o >>= 1) ss += __shfl_down_sync(0xffffffffu, ss, o);
    __shared__ float sp[4];
    __shared__ float invs;
    if ((tid & 31) == 0) sp[tid >> 5] = ss;
    __syncthreads();
    if (tid == 0) {
        float t = sp[0] + sp[1] + sp[2] + sp[3];
        invs = 1.0f / fmaxf(sqrtf(t), 1e-12f);
    }
    __syncthreads();
    float iv = invs;
    __nv_bfloat162 p0 = __floats2bfloat162_rn(v.x * iv, v.y * iv);
    __nv_bfloat162 p1 = __floats2bfloat162_rn(v.z * iv, v.w * iv);
    uint2 pk; pk.x = *(uint32_t*)&p0; pk.y = *(uint32_t*)&p1;
    *(uint2*)(nbP<S>() + ((size_t)b * N + n) * D_ + tid * 4) = pk;
}

// ---------------- fused sim GEMM (bf16 tensor cores) + lse + positive-sum ----------------
#define BM 128
#define BN 128
#define BK 32
#define SKEW 8
#define NKT (D_ / BK)   // 16

__device__ __forceinline__ void cp_async16(void* smem_dst, const void* gmem_src) {
    uint32_t d = (uint32_t)__cvta_generic_to_shared(smem_dst);
    asm volatile("cp.async.cg.shared.global [%0], [%1], 16;\n" :: "r"(d), "l"(gmem_src));
}
__device__ __forceinline__ void cp_commit() { asm volatile("cp.async.commit_group;\n"); }
template<int NN> __device__ __forceinline__ void cp_wait() {
    asm volatile("cp.async.wait_group %0;\n" :: "n"(NN));
}

__device__ __forceinline__ void mma_bf16(float c[4],
    uint32_t a0, uint32_t a1, uint32_t a2, uint32_t a3, uint32_t b0, uint32_t b1)
{
    asm volatile("mma.sync.aligned.m16n8k16.row.col.f32.bf16.bf16.f32 "
        "{%0,%1,%2,%3}, {%4,%5,%6,%7}, {%8,%9}, {%0,%1,%2,%3};\n"
        : "+f"(c[0]), "+f"(c[1]), "+f"(c[2]), "+f"(c[3])
        : "r"(a0), "r"(a1), "r"(a2), "r"(a3), "r"(b0), "r"(b1));
}

template<int S>
__global__ void __launch_bounds__(256, 2)
sim_kernel(int N)
{
    __shared__ __nv_bfloat16 As[2][BM][BK + SKEW];
    __shared__ __nv_bfloat16 Bs[2][BN][BK + SKEW];
    __shared__ float rsum[BM];
    __shared__ float rpos[BM];
    __shared__ int   erow[BM];
    __shared__ int   ecol[BN];
    __shared__ float part[8];

    const int tid  = threadIdx.x;
    const int lane = tid & 31;
    const int warp = tid >> 5;
    const int warpM = warp >> 1;          // 0..3 -> 32-row slab
    const int warpN = warp & 1;           // 0..1 -> 64-col slab
    const int qrow = lane >> 2;
    const int qk   = (lane & 3) * 2;

    const int rb = blockIdx.x * BM;
    const int b  = blockIdx.y;
    const __nv_bfloat16* base = nbP<S>() + (size_t)b * N * D_;
    const int* eidx = eidxP<S>();
    const int* cnt  = cntP<S>();

    if (tid < BM) { rsum[tid] = 0.f; rpos[tid] = 0.f; erow[tid] = eidx[rb + tid]; }

    const int r0 = tid >> 2, seg0 = tid & 3;          // op = tid
    const int r1 = (tid + 256) >> 2, seg1 = (tid + 256) & 3;

    const int nTiles = N / BN;
    for (int ct = 0; ct < nTiles; ++ct) {
        __syncthreads();   // previous epilogue done before ecol rewrite / smem reuse
        const int cb = ct * BN;
        if (tid < BN) ecol[tid] = eidx[cb + tid];

        float acc[2][8][4];
        #pragma unroll
        for (int mi = 0; mi < 2; mi++)
            #pragma unroll
            for (int ni = 0; ni < 8; ni++)
                #pragma unroll
                for (int r = 0; r < 4; r++) acc[mi][ni][r] = 0.f;

        // prologue: load kt=0 into buf 0
        {
            const int kb = 0;
            cp_async16(&As[0][r0][seg0 * 8], base + (size_t)(rb + r0) * D_ + kb + seg0 * 8);
            cp_async16(&Bs[0][r0][seg0 * 8], base + (size_t)(cb + r0) * D_ + kb + seg0 * 8);
            cp_async16(&As[0][r1][seg1 * 8], base + (size_t)(rb + r1) * D_ + kb + seg1 * 8);
            cp_async16(&Bs[0][r1][seg1 * 8], base + (size_t)(cb + r1) * D_ + kb + seg1 * 8);
            cp_commit();
        }

        int buf = 0;
        for (int kt = 0; kt < NKT; ++kt) {
            if (kt + 1 < NKT) {
                const int kb = (kt + 1) * BK;
                const int nb = buf ^ 1;
                cp_async16(&As[nb][r0][seg0 * 8], base + (size_t)(rb + r0) * D_ + kb + seg0 * 8);
                cp_async16(&Bs[nb][r0][seg0 * 8], base + (size_t)(cb + r0) * D_ + kb + seg0 * 8);
                cp_async16(&As[nb][r1][seg1 * 8], base + (size_t)(rb + r1) * D_ + kb + seg1 * 8);
                cp_async16(&Bs[nb][r1][seg1 * 8], base + (size_t)(cb + r1) * D_ + kb + seg1 * 8);
                cp_commit();
                cp_wait<1>();
            } else {
                cp_wait<0>();
            }
            __syncthreads();

            #pragma unroll
            for (int kk = 0; kk < BK; kk += 16) {
                uint32_t af[2][4];
                #pragma unroll
                for (int mi = 0; mi < 2; mi++) {
                    const __nv_bfloat16* ab = &As[buf][warpM * 32 + mi * 16 + qrow][kk + qk];
                    af[mi][0] = *(const uint32_t*)ab;
                    af[mi][1] = *(const uint32_t*)(ab + 8 * (BK + SKEW));
                    af[mi][2] = *(const uint32_t*)(ab + 8);
                    af[mi][3] = *(const uint32_t*)(ab + 8 * (BK + SKEW) + 8);
                }
                #pragma unroll
                for (int ni = 0; ni < 8; ni++) {
                    const __nv_bfloat16* bb = &Bs[buf][warpN * 64 + ni * 8 + qrow][kk + qk];
                    uint32_t b0 = *(const uint32_t*)bb;
                    uint32_t b1 = *(const uint32_t*)(bb + 8);
                    mma_bf16(acc[0][ni], af[0][0], af[0][1], af[0][2], af[0][3], b0, b1);
                    mma_bf16(acc[1][ni], af[1][0], af[1][1], af[1][2], af[1][3], b0, b1);
                }
            }
            __syncthreads();   // guard next cp.async overwrite of buf^1
            buf ^= 1;
        }

        // epilogue: lse partial sums + positive sums for this 128-col tile
        #pragma unroll
        for (int mi = 0; mi < 2; mi++) {
            #pragma unroll
            for (int h = 0; h < 2; h++) {
                int lrow = warpM * 32 + mi * 16 + qrow + h * 8;
                int rn = rb + lrow;
                int en = erow[lrow];
                float se = 0.f, pl = 0.f;
                #pragma unroll
                for (int ni = 0; ni < 8; ni++) {
                    #pragma unroll
                    for (int c = 0; c < 2; c++) {
                        float s = acc[mi][ni][h * 2 + c] * 10.0f;   // / tau
                        se += __expf(s - 10.0f);                    // diag==max~10: fixed shift
                        int lcol = warpN * 64 + ni * 8 + (lane & 3) * 2 + c;
                        int m = cb + lcol;
                        if (en >= 0 && ecol[lcol] == en && m != rn) pl += s;
                    }
                }
                se += __shfl_xor_sync(0xffffffffu, se, 1);
                se += __shfl_xor_sync(0xffffffffu, se, 2);
                pl += __shfl_xor_sync(0xffffffffu, pl, 1);
                pl += __shfl_xor_sync(0xffffffffu, pl, 2);
                if ((lane & 3) == 0) {
                    atomicAdd(&rsum[lrow], se);
                    atomicAdd(&rpos[lrow], pl);
                }
            }
        }
    }

    __syncthreads();
    float contrib = 0.f;
    if (tid < BM) {
        int c = cnt[rb + tid];
        if (c > 0) contrib = 10.0f + logf(rsum[tid]) - rpos[tid] / (float)c;
    }
    #pragma unroll
    for (int o = 16; o > 0; o >>= 1) contrib += __shfl_down_sync(0xffffffffu, contrib, o);
    if (lane == 0) part[warp] = contrib;
    __syncthreads();
    if (tid == 0) {
        float t = 0.f;
        #pragma unroll
        for (int i = 0; i < 8; i++) t += part[i];
        atomicAdd(&g_loss[S], (double)t);
    }
}

// ---------------- finalize ----------------
__global__ void final_kernel(float* out_loss)
{
    double l = 0.0;
    #pragma unroll
    for (int s = 0; s < 2; s++) {
        int nv = g_nvalid[s];
        if (nv > 0) l += g_loss[s] / (double)(B_ * nv);
    }
    *out_loss = (float)l;
}

// ---------------- launch ----------------
extern "C" void kernel_launch(void* const* d_in, const int* in_sizes, int n_in,
                              void* d_out, int out_size)
{
    const float* x0   = (const float*)d_in[0];
    const float* x1   = (const float*)d_in[1];
    const float* w0   = (const float*)d_in[2];
    const float* w1   = (const float*)d_in[3];
    const float* hy0  = (const float*)d_in[4];
    const float* hy1  = (const float*)d_in[5];
    const float* nod0 = (const float*)d_in[6];
    const float* nod1 = (const float*)d_in[7];
    float* out = (float*)d_out;

    float* adj0  = out;
    float* adj1  = out + (size_t)N0_ * H0_;
    float* lossp = out + (size_t)N0_ * H0_ + (size_t)N1_ * H1_;

    init_kernel<<<1, 1>>>();

    adj_kernel<0><<<N0_, 128>>>(nod0, hy0, adj0, H0_);
    cnt_kernel<0><<<1, 256>>>(N0_, H0_);
    norm_kernel<0><<<dim3(N0_, B_), 128>>>(x0, w0, L0_, N0_);
    sim_kernel<0><<<dim3(N0_ / BM, B_), 256>>>(N0_);

    adj_kernel<1><<<N1_, 128>>>(nod1, hy1, adj1, H1_);
    cnt_kernel<1><<<1, 256>>>(N1_, H1_);
    norm_kernel<1><<<dim3(N1_, B_), 128>>>(x1, w1, L1_, N1_);
    sim_kernel<1><<<dim3(N1_ / BM, B_), 256>>>(N1_);

    final_kernel<<<1, 1>>>(lossp);
}

// round 3
// speedup vs baseline: 6.4605x; 1.3677x over previous
#include <cuda_runtime.h>
#include <cuda_bf16.h>
#include <cstdint>

// ---------------- fixed problem shape ----------------
#define B_   64
#define D_   512
#define L0_  512
#define L1_  256
#define WS_  128
#define H0_  128
#define H1_  64
#define N0_  (L0_ + WS_)   // 640
#define N1_  (L1_ + WS_)   // 384

// ---------------- device scratch ----------------
__device__ __nv_bfloat16 g_nx0[(size_t)B_ * L0_ * D_];   // normalized x rows, bf16
__device__ __nv_bfloat16 g_nx1[(size_t)B_ * L1_ * D_];
__device__ __nv_bfloat16 g_nw0[(size_t)WS_ * D_];        // normalized word rows (batch-invariant)
__device__ __nv_bfloat16 g_nw1[(size_t)WS_ * D_];
__device__ int    g_eidx0[N0_], g_eidx1[N1_];
__device__ int    g_cnt0[N0_],  g_cnt1[N1_];
__device__ int    g_nvalid[2];
__device__ double g_loss[2];

// per-(b,n) accumulators: sum of exp(s-10) and sum of positive s
#define GS0 0
#define GP0 (B_ * N0_)
#define GS1 (2 * B_ * N0_)
#define GP1 (2 * B_ * N0_ + B_ * N1_)
#define GACC_TOT (2 * B_ * N0_ + 2 * B_ * N1_)   // 131072
__device__ float g_acc[GACC_TOT];

template<int S> __device__ __forceinline__ int* eidxP() { return S ? g_eidx1 : g_eidx0; }
template<int S> __device__ __forceinline__ int* cntP()  { return S ? g_cnt1  : g_cnt0;  }

// ---------------- init: zero accumulators (graph replays!) ----------------
__global__ void init_kernel() {
    int i = blockIdx.x * blockDim.x + threadIdx.x;
    if (i < GACC_TOT) g_acc[i] = 0.f;
    if (i == 0) { g_loss[0] = 0.0; g_loss[1] = 0.0; }
}

// ---------------- adjacency: adj_bin = softmax(relu(3*enod@ehy^T)) > 0.5 ----------------
// softmax row sums to 1 => at most one entry > 0.5 and it is the row max =>
// always inside top-k: adj_bin = (p > 0.5). No top-k machinery needed.
template<int S>
__global__ void __launch_bounds__(128)
adj_kernel(const float* __restrict__ enod, const float* __restrict__ ehy,
           float* __restrict__ adj_out, int H)
{
    const int n   = blockIdx.x;
    const int tid = threadIdx.x;

    __shared__ float xrow[D_];
    __shared__ float et[128][33];
    __shared__ float rbuf[128];
    __shared__ int   widx;

    *(float4*)&xrow[tid * 4] = *(const float4*)(enod + (size_t)n * D_ + tid * 4);

    float acc = 0.f;
    const int nf4 = H * 8;
    for (int kk = 0; kk < D_; kk += 32) {
        __syncthreads();
        for (int f = tid; f < nf4; f += 128) {
            int h = f >> 3, c4 = f & 7;
            float4 v = *(const float4*)(ehy + (size_t)h * D_ + kk + c4 * 4);
            et[h][c4 * 4 + 0] = v.x; et[h][c4 * 4 + 1] = v.y;
            et[h][c4 * 4 + 2] = v.z; et[h][c4 * 4 + 3] = v.w;
        }
        __syncthreads();
        if (tid < H) {
            #pragma unroll
            for (int c = 0; c < 32; c++) acc += xrow[kk + c] * et[tid][c];
        }
    }

    float z = (tid < H) ? fmaxf(3.0f * acc, 0.0f) : -1e30f;
    rbuf[tid] = z; __syncthreads();
    for (int o = 64; o > 0; o >>= 1) { if (tid < o) rbuf[tid] = fmaxf(rbuf[tid], rbuf[tid + o]); __syncthreads(); }
    float zmax = rbuf[0]; __syncthreads();
    float e = (tid < H) ? __expf(z - zmax) : 0.f;
    rbuf[tid] = e; __syncthreads();
    for (int o = 64; o > 0; o >>= 1) { if (tid < o) rbuf[tid] += rbuf[tid + o]; __syncthreads(); }
    float ssum = rbuf[0];
    if (tid == 0) widx = -1;
    __syncthreads();
    if (tid < H) {
        int bin = (e / ssum) > 0.5f;
        adj_out[(size_t)n * H + tid] = (float)bin;
        if (bin) widx = tid;
    }
    __syncthreads();
    if (tid == 0) eidxP<S>()[n] = widx;
}

// ---------------- counts ----------------
template<int S>
__global__ void cnt_kernel(int N, int H)
{
    __shared__ int hist[128];
    __shared__ int vcount;
    const int tid = threadIdx.x;
    if (tid < H) hist[tid] = 0;
    if (tid == 0) vcount = 0;
    __syncthreads();
    for (int n = tid; n < N; n += blockDim.x) {
        int e = eidxP<S>()[n];
        if (e >= 0) atomicAdd(&hist[e], 1);
    }
    __syncthreads();
    int local = 0;
    for (int n = tid; n < N; n += blockDim.x) {
        int e = eidxP<S>()[n];
        int c = (e >= 0) ? hist[e] - 1 : 0;
        cntP<S>()[n] = c;
        if (c > 0) local++;
    }
    atomicAdd(&vcount, local);
    __syncthreads();
    if (tid == 0) g_nvalid[S] = vcount;
}

// ---------------- normalize -> bf16 (warp-per-row) ----------------
__global__ void __launch_bounds__(256)
normx_kernel(const float* __restrict__ x, __nv_bfloat16* __restrict__ dst, int nrows)
{
    const int gw   = (blockIdx.x * 256 + threadIdx.x) >> 5;
    const int lane = threadIdx.x & 31;
    if (gw >= nrows) return;
    const float* src = x + (size_t)gw * D_;
    float4 v[4];
    #pragma unroll
    for (int i = 0; i < 4; i++) v[i] = *(const float4*)(src + i * 128 + lane * 4);
    float ss = 0.f;
    #pragma unroll
    for (int i = 0; i < 4; i++) ss += v[i].x*v[i].x + v[i].y*v[i].y + v[i].z*v[i].z + v[i].w*v[i].w;
    #pragma unroll
    for (int o = 16; o > 0; o >>= 1) ss += __shfl_xor_sync(0xffffffffu, ss, o);
    float iv = 1.0f / fmaxf(sqrtf(ss), 1e-12f);
    __nv_bfloat16* drow = dst + (size_t)gw * D_;
    #pragma unroll
    for (int i = 0; i < 4; i++) {
        __nv_bfloat162 p0 = __floats2bfloat162_rn(v[i].x * iv, v[i].y * iv);
        __nv_bfloat162 p1 = __floats2bfloat162_rn(v[i].z * iv, v[i].w * iv);
        uint2 pk; pk.x = *(uint32_t*)&p0; pk.y = *(uint32_t*)&p1;
        *(uint2*)(drow + i * 128 + lane * 4) = pk;
    }
}

// ---------------- fp32 exp2 polynomial on the FMA pipe (offloads MUFU) ----------------
__device__ __forceinline__ float poly_exp2(float x)
{
    float r = x + 12582912.0f;                 // round-to-nearest int (magic)
    int   n = __float_as_int(r) - 0x4B400000;
    float f = x - (r - 12582912.0f);           // f in [-0.5, 0.5]
    float p = 0.0013333558f;
    p = fmaf(p, f, 0.0096181291f);
    p = fmaf(p, f, 0.0555041087f);
    p = fmaf(p, f, 0.2402265070f);
    p = fmaf(p, f, 0.6931471806f);
    p = fmaf(p, f, 1.0f);
    return __int_as_float(__float_as_int(p) + (n << 23));
}

// ---------------- fused sim GEMM (bf16 mma) + symmetric lse/positive accumulation ----------------
#define BM 128
#define BN 128
#define BK 32
#define SKEW 8
#define NKT (D_ / BK)   // 16

__device__ __forceinline__ void cp_async16(void* smem_dst, const void* gmem_src) {
    uint32_t d = (uint32_t)__cvta_generic_to_shared(smem_dst);
    asm volatile("cp.async.cg.shared.global [%0], [%1], 16;\n" :: "r"(d), "l"(gmem_src));
}
__device__ __forceinline__ void cp_commit() { asm volatile("cp.async.commit_group;\n"); }
template<int NN> __device__ __forceinline__ void cp_wait() {
    asm volatile("cp.async.wait_group %0;\n" :: "n"(NN));
}

__device__ __forceinline__ void mma_bf16(float c[4],
    uint32_t a0, uint32_t a1, uint32_t a2, uint32_t a3, uint32_t b0, uint32_t b1)
{
    asm volatile("mma.sync.aligned.m16n8k16.row.col.f32.bf16.bf16.f32 "
        "{%0,%1,%2,%3}, {%4,%5,%6,%7}, {%8,%9}, {%0,%1,%2,%3};\n"
        : "+f"(c[0]), "+f"(c[1]), "+f"(c[2]), "+f"(c[3])
        : "r"(a0), "r"(a1), "r"(a2), "r"(a3), "r"(b0), "r"(b1));
}

// one CTA = one (row-tile, col-tile) pair with ct >= rt, full K=512.
template<int S>
__global__ void __launch_bounds__(256, 2)
sim_kernel(const __nv_bfloat16* __restrict__ nx, const __nv_bfloat16* __restrict__ nw,
           int N, int L, float* __restrict__ gsum, float* __restrict__ gpos)
{
    __shared__ __nv_bfloat16 As[2][BM][BK + SKEW];
    __shared__ __nv_bfloat16 Bs[2][BN][BK + SKEW];
    __shared__ float rsum[BM], rpos[BM], csum[BN], cpos[BN];
    __shared__ int   erow[BM], ecol[BN];

    const int tid  = threadIdx.x;
    const int lane = tid & 31;
    const int warp = tid >> 5;
    const int warpM = warp >> 1;
    const int warpN = warp & 1;
    const int qrow = lane >> 2;
    const int qk   = (lane & 3) * 2;

    // decode triangular pair index
    const int T = N >> 7;
    int p = blockIdx.x, rt = 0;
    while (p >= T - rt) { p -= T - rt; rt++; }
    const int ct = rt + p;
    const bool diag = (rt == ct);

    const int rb = rt * BM, cb = ct * BN;
    const int b  = blockIdx.y;

    const __nv_bfloat16* baseA = (rb < L) ? nx + ((size_t)b * L + rb) * D_
                                          : nw + (size_t)(rb - L) * D_;
    const __nv_bfloat16* baseB = (cb < L) ? nx + ((size_t)b * L + cb) * D_
                                          : nw + (size_t)(cb - L) * D_;
    const int* eidx = eidxP<S>();

    if (tid < BM) {
        rsum[tid] = 0.f; rpos[tid] = 0.f; csum[tid] = 0.f; cpos[tid] = 0.f;
        erow[tid] = eidx[rb + tid]; ecol[tid] = eidx[cb + tid];
    }

    const int r0 = tid >> 2, seg0 = tid & 3;
    const int r1 = (tid + 256) >> 2, seg1 = (tid + 256) & 3;

    float acc[2][8][4];
    #pragma unroll
    for (int mi = 0; mi < 2; mi++)
        #pragma unroll
        for (int ni = 0; ni < 8; ni++)
            #pragma unroll
            for (int r = 0; r < 4; r++) acc[mi][ni][r] = 0.f;

    // prologue
    cp_async16(&As[0][r0][seg0 * 8], baseA + (size_t)r0 * D_ + seg0 * 8);
    cp_async16(&Bs[0][r0][seg0 * 8], baseB + (size_t)r0 * D_ + seg0 * 8);
    cp_async16(&As[0][r1][seg1 * 8], baseA + (size_t)r1 * D_ + seg1 * 8);
    cp_async16(&Bs[0][r1][seg1 * 8], baseB + (size_t)r1 * D_ + seg1 * 8);
    cp_commit();

    int buf = 0;
    for (int kt = 0; kt < NKT; ++kt) {
        if (kt + 1 < NKT) {
            const int kb = (kt + 1) * BK;
            const int nb = buf ^ 1;
            cp_async16(&As[nb][r0][seg0 * 8], baseA + (size_t)r0 * D_ + kb + seg0 * 8);
            cp_async16(&Bs[nb][r0][seg0 * 8], baseB + (size_t)r0 * D_ + kb + seg0 * 8);
            cp_async16(&As[nb][r1][seg1 * 8], baseA + (size_t)r1 * D_ + kb + seg1 * 8);
            cp_async16(&Bs[nb][r1][seg1 * 8], baseB + (size_t)r1 * D_ + kb + seg1 * 8);
            cp_commit();
            cp_wait<1>();
        } else {
            cp_wait<0>();
        }
        __syncthreads();

        #pragma unroll
        for (int kk = 0; kk < BK; kk += 16) {
            uint32_t af[2][4];
            #pragma unroll
            for (int mi = 0; mi < 2; mi++) {
                const __nv_bfloat16* ab = &As[buf][warpM * 32 + mi * 16 + qrow][kk + qk];
                af[mi][0] = *(const uint32_t*)ab;
                af[mi][1] = *(const uint32_t*)(ab + 8 * (BK + SKEW));
                af[mi][2] = *(const uint32_t*)(ab + 8);
                af[mi][3] = *(const uint32_t*)(ab + 8 * (BK + SKEW) + 8);
            }
            #pragma unroll
            for (int ni = 0; ni < 8; ni++) {
                const __nv_bfloat16* bb = &Bs[buf][warpN * 64 + ni * 8 + qrow][kk + qk];
                uint32_t b0 = *(const uint32_t*)bb;
                uint32_t b1 = *(const uint32_t*)(bb + 8);
                mma_bf16(acc[0][ni], af[0][0], af[0][1], af[0][2], af[0][3], b0, b1);
                mma_bf16(acc[1][ni], af[1][0], af[1][1], af[1][2], af[1][3], b0, b1);
            }
        }
        __syncthreads();
        buf ^= 1;
    }

    // ---- epilogue: exp + symmetric row/col accumulation ----
    const float C2 = 14.4269504089f;   // 10*log2(e); exp(s-10) = 2^(a*C2 - C2), s = 10a
    float rowS[2][2] = {{0,0},{0,0}}, rowP[2][2] = {{0,0},{0,0}};
    float colS[8][2], colP[8][2];
    #pragma unroll
    for (int ni = 0; ni < 8; ni++) { colS[ni][0]=0; colS[ni][1]=0; colP[ni][0]=0; colP[ni][1]=0; }

    #pragma unroll
    for (int mi = 0; mi < 2; mi++) {
        #pragma unroll
        for (int h = 0; h < 2; h++) {
            const int lrow = warpM * 32 + mi * 16 + h * 8 + qrow;
            const int rn = rb + lrow;
            const int en = erow[lrow];
            #pragma unroll
            for (int ni = 0; ni < 8; ni++) {
                #pragma unroll
                for (int c = 0; c < 2; c++) {
                    const int lcol = warpN * 64 + ni * 8 + (lane & 3) * 2 + c;
                    const int m = cb + lcol;
                    const float a = acc[mi][ni][h * 2 + c];
                    if (!diag || m > rn) {
                        float x = fmaf(a, C2, -C2);
                        float e = (ni < 3) ? poly_exp2(x) : exp2f(x);  // split MUFU/FMA pipes
                        rowS[mi][h] += e; colS[ni][c] += e;
                        if (en >= 0 && ecol[lcol] == en) {
                            float s = a * 10.0f;
                            rowP[mi][h] += s; colP[ni][c] += s;
                        }
                    } else if (m == rn) {
                        rowS[mi][h] += 1.0f;   // exact diagonal term
                    }
                }
            }
        }
    }

    // row reductions (4 lanes share a row)
    #pragma unroll
    for (int mi = 0; mi < 2; mi++) {
        #pragma unroll
        for (int h = 0; h < 2; h++) {
            float v = rowS[mi][h], w = rowP[mi][h];
            v += __shfl_xor_sync(0xffffffffu, v, 1);
            v += __shfl_xor_sync(0xffffffffu, v, 2);
            w += __shfl_xor_sync(0xffffffffu, w, 1);
            w += __shfl_xor_sync(0xffffffffu, w, 2);
            if ((lane & 3) == 0) {
                const int lrow = warpM * 32 + mi * 16 + h * 8 + qrow;
                atomicAdd(&rsum[lrow], v);
                atomicAdd(&rpos[lrow], w);
            }
        }
    }
    // column reductions (8 lanes stride-4 share a column)
    #pragma unroll
    for (int ni = 0; ni < 8; ni++) {
        #pragma unroll
        for (int c = 0; c < 2; c++) {
            float v = colS[ni][c], w = colP[ni][c];
            v += __shfl_xor_sync(0xffffffffu, v, 4);
            v += __shfl_xor_sync(0xffffffffu, v, 8);
            v += __shfl_xor_sync(0xffffffffu, v, 16);
            w += __shfl_xor_sync(0xffffffffu, w, 4);
            w += __shfl_xor_sync(0xffffffffu, w, 8);
            w += __shfl_xor_sync(0xffffffffu, w, 16);
            if (qrow == 0) {
                const int lcol = warpN * 64 + ni * 8 + (lane & 3) * 2 + c;
                atomicAdd(&csum[lcol], v);
                atomicAdd(&cpos[lcol], w);
            }
        }
    }

    __syncthreads();
    if (tid < BM) {
        const size_t bofs = (size_t)b * N;
        float rs = rsum[tid], rp = rpos[tid];
        if (diag) { rs += csum[tid]; rp += cpos[tid]; }
        atomicAdd(gsum + bofs + rb + tid, rs);
        atomicAdd(gpos + bofs + rb + tid, rp);
        if (!diag) {
            atomicAdd(gsum + bofs + cb + tid, csum[tid]);
            atomicAdd(gpos + bofs + cb + tid, cpos[tid]);
        }
    }
}

// ---------------- per-scale loss reduction ----------------
template<int S>
__global__ void __launch_bounds__(256)
reduce_kernel(int N)
{
    const float* gsum = g_acc + (S ? GS1 : GS0);
    const float* gpos = g_acc + (S ? GP1 : GP0);
    const int* cnt = cntP<S>();
    const int b = blockIdx.x, tid = threadIdx.x;
    float local = 0.f;
    for (int n = tid; n < N; n += 256) {
        int c = cnt[n];
        if (c > 0) {
            float rs = gsum[(size_t)b * N + n];
            local += 10.0f + __logf(rs) - gpos[(size_t)b * N + n] / (float)c;
        }
    }
    #pragma unroll
    for (int o = 16; o > 0; o >>= 1) local += __shfl_down_sync(0xffffffffu, local, o);
    __shared__ float sp[8];
    if ((tid & 31) == 0) sp[tid >> 5] = local;
    __syncthreads();
    if (tid == 0) {
        float t = 0.f;
        #pragma unroll
        for (int i = 0; i < 8; i++) t += sp[i];
        atomicAdd(&g_loss[S], (double)t);
    }
}

// ---------------- finalize ----------------
__global__ void final_kernel(float* out_loss)
{
    double l = 0.0;
    #pragma unroll
    for (int s = 0; s < 2; s++) {
        int nv = g_nvalid[s];
        if (nv > 0) l += g_loss[s] / (double)(B_ * nv);
    }
    *out_loss = (float)l;
}

// ---------------- launch ----------------
extern "C" void kernel_launch(void* const* d_in, const int* in_sizes, int n_in,
                              void* d_out, int out_size)
{
    const float* x0   = (const float*)d_in[0];
    const float* x1   = (const float*)d_in[1];
    const float* w0   = (const float*)d_in[2];
    const float* w1   = (const float*)d_in[3];
    const float* hy0  = (const float*)d_in[4];
    const float* hy1  = (const float*)d_in[5];
    const float* nod0 = (const float*)d_in[6];
    const float* nod1 = (const float*)d_in[7];
    float* out = (float*)d_out;

    float* adj0  = out;
    float* adj1  = out + (size_t)N0_ * H0_;
    float* lossp = out + (size_t)N0_ * H0_ + (size_t)N1_ * H1_;

    __nv_bfloat16 *nx0, *nx1, *nw0, *nw1;
    float* gacc;
    cudaGetSymbolAddress((void**)&nx0, g_nx0);
    cudaGetSymbolAddress((void**)&nx1, g_nx1);
    cudaGetSymbolAddress((void**)&nw0, g_nw0);
    cudaGetSymbolAddress((void**)&nw1, g_nw1);
    cudaGetSymbolAddress((void**)&gacc, g_acc);

    init_kernel<<<(GACC_TOT + 255) / 256, 256>>>();

    adj_kernel<0><<<N0_, 128>>>(nod0, hy0, adj0, H0_);
    adj_kernel<1><<<N1_, 128>>>(nod1, hy1, adj1, H1_);
    cnt_kernel<0><<<1, 256>>>(N0_, H0_);
    cnt_kernel<1><<<1, 256>>>(N1_, H1_);

    normx_kernel<<<(B_ * L0_) / 8, 256>>>(x0, nx0, B_ * L0_);
    normx_kernel<<<(B_ * L1_) / 8, 256>>>(x1, nx1, B_ * L1_);
    normx_kernel<<<WS_ / 8, 256>>>(w0, nw0, WS_);
    normx_kernel<<<WS_ / 8, 256>>>(w1, nw1, WS_);

    const int T0 = N0_ / BM, P0 = T0 * (T0 + 1) / 2;   // 15
    const int T1 = N1_ / BM, P1 = T1 * (T1 + 1) / 2;   // 6
    sim_kernel<0><<<dim3(P0, B_), 256>>>(nx0, nw0, N0_, L0_, gacc + GS0, gacc + GP0);
    sim_kernel<1><<<dim3(P1, B_), 256>>>(nx1, nw1, N1_, L1_, gacc + GS1, gacc + GP1);

    reduce_kernel<0><<<B_, 256>>>(N0_);
    reduce_kernel<1><<<B_, 256>>>(N1_);

    final_kernel<<<1, 1>>>(lossp);
}

// round 4
// speedup vs baseline: 7.1902x; 1.1129x over previous
#include <cuda_runtime.h>
#include <cuda_bf16.h>
#include <cuda_fp16.h>
#include <cstdint>

// ---------------- fixed problem shape ----------------
#define B_   64
#define D_   512
#define L0_  512
#define L1_  256
#define WS_  128
#define H0_  128
#define H1_  64
#define N0_  (L0_ + WS_)   // 640
#define N1_  (L1_ + WS_)   // 384
#define HT_  (H0_ + H1_)   // 192
#define P0_  15            // 5*6/2 triangular tile pairs, scale0
#define P1_  6             // 3*4/2, scale1

// ---------------- device scratch ----------------
__device__ __nv_bfloat16 g_nx0[(size_t)B_ * L0_ * D_];
__device__ __nv_bfloat16 g_nx1[(size_t)B_ * L1_ * D_];
__device__ __nv_bfloat16 g_nw0[WS_ * D_];
__device__ __nv_bfloat16 g_nw1[WS_ * D_];
__device__ float g_selfx0[B_ * L0_];
__device__ float g_selfx1[B_ * L1_];
__device__ float g_selfw0[WS_];
__device__ float g_selfw1[WS_];
__device__ int   g_eidx0[N0_], g_eidx1[N1_];
__device__ int   g_memb0[N0_], g_memb1[N1_];
__device__ int   g_gstart0[H0_ + 1], g_gstart1[H1_ + 1];
__device__ int   g_cnt0[N0_], g_cnt1[N1_];
__device__ int   g_nvalid[2];
__device__ float g_posg[B_ * HT_];
#define GSUMTOT (B_ * (N0_ + N1_))
__device__ float g_gsum[GSUMTOT];   // scale0 at 0, scale1 at B_*N0_
__device__ double g_loss[2];

// ---------------- init (graph replays -> re-zero every launch) ----------------
__global__ void init_kernel() {
    int i = blockIdx.x * blockDim.x + threadIdx.x;
    if (i < GSUMTOT) g_gsum[i] = 0.f;
    if (i == 0) { g_loss[0] = 0.0; g_loss[1] = 0.0; }
}

// ---------------- adjacency: adj_bin = softmax(relu(3*enod@ehy^T)) > 0.5 ----------------
// softmax row sums to 1 => at most one entry > 0.5 and it is the row max =>
// always inside top-k: adj_bin = (p > 0.5). No top-k machinery needed.
template<int S>
__global__ void __launch_bounds__(128)
adj_kernel(const float* __restrict__ enod, const float* __restrict__ ehy,
           float* __restrict__ adj_out, int H)
{
    const int n   = blockIdx.x;
    const int tid = threadIdx.x;

    __shared__ float xrow[D_];
    __shared__ float et[128][36];     // 36-float stride: LDS.128 conflict-free
    __shared__ float rbuf[128];
    __shared__ int   widx;

    *(float4*)&xrow[tid * 4] = *(const float4*)(enod + (size_t)n * D_ + tid * 4);

    float acc = 0.f;
    const int nf4 = H * 8;
    for (int kk = 0; kk < D_; kk += 32) {
        __syncthreads();
        for (int f = tid; f < nf4; f += 128) {
            int h = f >> 3, c4 = f & 7;
            *(float4*)&et[h][c4 * 4] = *(const float4*)(ehy + (size_t)h * D_ + kk + c4 * 4);
        }
        __syncthreads();
        if (tid < H) {
            #pragma unroll
            for (int c4 = 0; c4 < 8; c4++) {
                float4 e4 = *(const float4*)&et[tid][c4 * 4];
                float4 x4 = *(const float4*)&xrow[kk + c4 * 4];
                acc = fmaf(x4.x, e4.x, acc);
                acc = fmaf(x4.y, e4.y, acc);
                acc = fmaf(x4.z, e4.z, acc);
                acc = fmaf(x4.w, e4.w, acc);
            }
        }
    }

    float z = (tid < H) ? fmaxf(3.0f * acc, 0.0f) : -1e30f;
    rbuf[tid] = z; __syncthreads();
    for (int o = 64; o > 0; o >>= 1) { if (tid < o) rbuf[tid] = fmaxf(rbuf[tid], rbuf[tid + o]); __syncthreads(); }
    float zmax = rbuf[0]; __syncthreads();
    float e = (tid < H) ? __expf(z - zmax) : 0.f;
    rbuf[tid] = e; __syncthreads();
    for (int o = 64; o > 0; o >>= 1) { if (tid < o) rbuf[tid] += rbuf[tid + o]; __syncthreads(); }
    float ssum = rbuf[0];
    if (tid == 0) widx = -1;
    __syncthreads();
    if (tid < H) {
        int bin = (e / ssum) > 0.5f;
        adj_out[(size_t)n * H + tid] = (float)bin;
        if (bin) widx = tid;
    }
    __syncthreads();
    if (tid == 0) { if (S) g_eidx1[n] = widx; else g_eidx0[n] = widx; }
}

// ---------------- counts + group member lists (1 launch, block per scale) ----------------
__global__ void __launch_bounds__(256)
cnt_kernel()
{
    const int S = blockIdx.x;
    const int N = S ? N1_ : N0_;
    const int H = S ? H1_ : H0_;
    const int* eidx = S ? g_eidx1 : g_eidx0;
    int* memb = S ? g_memb1 : g_memb0;
    int* gst  = S ? g_gstart1 : g_gstart0;
    int* cnt  = S ? g_cnt1 : g_cnt0;

    __shared__ int sz[128];
    __shared__ int cur[128];
    __shared__ int vc;
    const int tid = threadIdx.x;
    if (tid < H) sz[tid] = 0;
    if (tid == 0) vc = 0;
    __syncthreads();
    for (int n = tid; n < N; n += 256) {
        int e = eidx[n];
        if (e >= 0) atomicAdd(&sz[e], 1);
    }
    __syncthreads();
    if (tid == 0) {
        int acc = 0;
        for (int k = 0; k < H; k++) { gst[k] = acc; cur[k] = acc; acc += sz[k]; }
        gst[H] = acc;
    }
    __syncthreads();
    int local = 0;
    for (int n = tid; n < N; n += 256) {
        int e = eidx[n];
        int c = 0;
        if (e >= 0) {
            int p = atomicAdd(&cur[e], 1);
            memb[p] = n;
            c = sz[e] - 1;
        }
        cnt[n] = c;
        if (c > 0) local++;
    }
    atomicAdd(&vc, local);
    __syncthreads();
    if (tid == 0) g_nvalid[S] = vc;
}

// ---------------- normalize -> bf16 + self-dot (warp-per-row) ----------------
__global__ void __launch_bounds__(256)
normx_kernel(const float* __restrict__ x, __nv_bfloat16* __restrict__ dst,
             float* __restrict__ selfout, int nrows)
{
    const int gw   = (blockIdx.x * 256 + threadIdx.x) >> 5;
    const int lane = threadIdx.x & 31;
    if (gw >= nrows) return;
    const float* src = x + (size_t)gw * D_;
    float4 v[4];
    #pragma unroll
    for (int i = 0; i < 4; i++) v[i] = *(const float4*)(src + i * 128 + lane * 4);
    float ss = 0.f;
    #pragma unroll
    for (int i = 0; i < 4; i++) ss += v[i].x*v[i].x + v[i].y*v[i].y + v[i].z*v[i].z + v[i].w*v[i].w;
    #pragma unroll
    for (int o = 16; o > 0; o >>= 1) ss += __shfl_xor_sync(0xffffffffu, ss, o);
    float iv = 1.0f / fmaxf(sqrtf(ss), 1e-12f);
    __nv_bfloat16* drow = dst + (size_t)gw * D_;
    float sd = 0.f;
    #pragma unroll
    for (int i = 0; i < 4; i++) {
        __nv_bfloat162 p0 = __floats2bfloat162_rn(v[i].x * iv, v[i].y * iv);
        __nv_bfloat162 p1 = __floats2bfloat162_rn(v[i].z * iv, v[i].w * iv);
        float2 f0 = __bfloat1622float2(p0);
        float2 f1 = __bfloat1622float2(p1);
        sd += f0.x*f0.x + f0.y*f0.y + f1.x*f1.x + f1.y*f1.y;
        uint2 pk; pk.x = *(uint32_t*)&p0; pk.y = *(uint32_t*)&p1;
        *(uint2*)(drow + i * 128 + lane * 4) = pk;
    }
    #pragma unroll
    for (int o = 16; o > 0; o >>= 1) sd += __shfl_xor_sync(0xffffffffu, sd, o);
    if (lane == 0) selfout[gw] = sd;
}

// ---------------- per-(b,edge) positive group sums ----------------
// sum_{n!=m in group} s_nm = 10*(||sum of rows||^2 - sum selfdot); all cnt in
// group equal sz-1, so the loss only needs this per-group total / (sz-1).
__global__ void __launch_bounds__(128)
posg_kernel()
{
    const int kg = blockIdx.x;
    const int S  = (kg >= H0_);
    const int k  = S ? kg - H0_ : kg;
    const int b  = blockIdx.y;
    const int tid = threadIdx.x;

    const int* gst  = S ? g_gstart1 : g_gstart0;
    const int* memb = S ? g_memb1 : g_memb0;
    const int L = S ? L1_ : L0_;
    const __nv_bfloat16* nx = S ? g_nx1 : g_nx0;
    const __nv_bfloat16* nw = S ? g_nw1 : g_nw0;
    const float* selfx = S ? g_selfx1 : g_selfx0;
    const float* selfw = S ? g_selfw1 : g_selfw0;

    const int s0 = gst[k], s1 = gst[k + 1];
    const int szk = s1 - s0;
    float* outp = &g_posg[b * HT_ + kg];
    if (szk < 2) { if (tid == 0) *outp = 0.f; return; }

    float g0 = 0.f, g1 = 0.f, g2 = 0.f, g3 = 0.f;
    float selfs = 0.f;
    for (int i = s0; i < s1; i++) {
        int n = memb[i];
        const __nv_bfloat16* row = (n < L) ? nx + ((size_t)b * L + n) * D_
                                           : nw + (size_t)(n - L) * D_;
        uint2 u = *(const uint2*)(row + tid * 4);
        __nv_bfloat162 p0 = *(__nv_bfloat162*)&u.x;
        __nv_bfloat162 p1 = *(__nv_bfloat162*)&u.y;
        float2 f0 = __bfloat1622float2(p0);
        float2 f1 = __bfloat1622float2(p1);
        g0 += f0.x; g1 += f0.y; g2 += f1.x; g3 += f1.y;
    }
    for (int i = s0 + tid; i < s1; i += 128) {
        int n = memb[i];
        selfs += (n < L) ? selfx[(size_t)b * L + n] : selfw[n - L];
    }
    float val = g0*g0 + g1*g1 + g2*g2 + g3*g3;
    #pragma unroll
    for (int o = 16; o > 0; o >>= 1) {
        val   += __shfl_xor_sync(0xffffffffu, val, o);
        selfs += __shfl_xor_sync(0xffffffffu, selfs, o);
    }
    __shared__ float sv[4], sf[4];
    if ((tid & 31) == 0) { sv[tid >> 5] = val; sf[tid >> 5] = selfs; }
    __syncthreads();
    if (tid == 0) {
        float gv = sv[0] + sv[1] + sv[2] + sv[3];
        float sc = sf[0] + sf[1] + sf[2] + sf[3];
        *outp = 10.0f * (gv - sc) / (float)(szk - 1);
    }
}

// ---------------- fused sim GEMM (bf16 mma) + f16x2-exp lse accumulation ----------------
#define BM 128
#define BN 128
#define BK 32
#define SKEW 8
#define NKT (D_ / BK)   // 16

__device__ __forceinline__ void cp_async16(void* smem_dst, const void* gmem_src) {
    uint32_t d = (uint32_t)__cvta_generic_to_shared(smem_dst);
    asm volatile("cp.async.cg.shared.global [%0], [%1], 16;\n" :: "r"(d), "l"(gmem_src));
}
__device__ __forceinline__ void cp_commit() { asm volatile("cp.async.commit_group;\n"); }
template<int NN> __device__ __forceinline__ void cp_wait() {
    asm volatile("cp.async.wait_group %0;\n" :: "n"(NN));
}
__device__ __forceinline__ void mma_bf16(float c[4],
    uint32_t a0, uint32_t a1, uint32_t a2, uint32_t a3, uint32_t b0, uint32_t b1)
{
    asm volatile("mma.sync.aligned.m16n8k16.row.col.f32.bf16.bf16.f32 "
        "{%0,%1,%2,%3}, {%4,%5,%6,%7}, {%8,%9}, {%0,%1,%2,%3};\n"
        : "+f"(c[0]), "+f"(c[1]), "+f"(c[2]), "+f"(c[3])
        : "r"(a0), "r"(a1), "r"(a2), "r"(a3), "r"(b0), "r"(b1));
}

// one CTA = one (rt,ct) tile pair, ct >= rt; both scales in one launch.
// accumulates 4096*exp(s-10) row sums (and col sums if off-diag) into g_gsum.
__global__ void __launch_bounds__(256, 2)
sim_kernel()
{
    __shared__ __nv_bfloat16 As[2][BM][BK + SKEW];
    __shared__ __nv_bfloat16 Bs[2][BN][BK + SKEW];
    __shared__ float rsmem[BM], csmem[BN];

    const int tid  = threadIdx.x;
    const int lane = tid & 31;
    const int warp = tid >> 5;
    const int warpM = warp >> 1;
    const int warpN = warp & 1;
    const int qrow = lane >> 2;
    const int qk   = (lane & 3) * 2;

    // decode scale + triangular pair
    int bx = blockIdx.x;
    const int S = (bx >= P0_);
    int p = S ? bx - P0_ : bx;
    const int T = S ? (N1_ >> 7) : (N0_ >> 7);
    int rt = 0;
    while (p >= T - rt) { p -= T - rt; rt++; }
    const int ct = rt + p;
    const bool diag = (rt == ct);

    const int rb = rt * BM, cb = ct * BN;
    const int b  = blockIdx.y;
    const int L = S ? L1_ : L0_;
    const int N = S ? N1_ : N0_;
    const __nv_bfloat16* nx = S ? g_nx1 : g_nx0;
    const __nv_bfloat16* nw = S ? g_nw1 : g_nw0;
    float* gsum = g_gsum + (S ? B_ * N0_ : 0) + (size_t)b * N;

    const __nv_bfloat16* baseA = (rb < L) ? nx + ((size_t)b * L + rb) * D_
                                          : nw + (size_t)(rb - L) * D_;
    const __nv_bfloat16* baseB = (cb < L) ? nx + ((size_t)b * L + cb) * D_
                                          : nw + (size_t)(cb - L) * D_;

    if (tid < BM) { rsmem[tid] = 0.f; csmem[tid] = 0.f; }

    const int r0 = tid >> 2, seg0 = tid & 3;
    const int r1 = (tid + 256) >> 2, seg1 = (tid + 256) & 3;

    float acc[2][8][4];
    #pragma unroll
    for (int mi = 0; mi < 2; mi++)
        #pragma unroll
        for (int ni = 0; ni < 8; ni++)
            #pragma unroll
            for (int r = 0; r < 4; r++) acc[mi][ni][r] = 0.f;

    cp_async16(&As[0][r0][seg0 * 8], baseA + (size_t)r0 * D_ + seg0 * 8);
    cp_async16(&Bs[0][r0][seg0 * 8], baseB + (size_t)r0 * D_ + seg0 * 8);
    cp_async16(&As[0][r1][seg1 * 8], baseA + (size_t)r1 * D_ + seg1 * 8);
    cp_async16(&Bs[0][r1][seg1 * 8], baseB + (size_t)r1 * D_ + seg1 * 8);
    cp_commit();

    int buf = 0;
    for (int kt = 0; kt < NKT; ++kt) {
        if (kt + 1 < NKT) {
            const int kb = (kt + 1) * BK;
            const int nb = buf ^ 1;
            cp_async16(&As[nb][r0][seg0 * 8], baseA + (size_t)r0 * D_ + kb + seg0 * 8);
            cp_async16(&Bs[nb][r0][seg0 * 8], baseB + (size_t)r0 * D_ + kb + seg0 * 8);
            cp_async16(&As[nb][r1][seg1 * 8], baseA + (size_t)r1 * D_ + kb + seg1 * 8);
            cp_async16(&Bs[nb][r1][seg1 * 8], baseB + (size_t)r1 * D_ + kb + seg1 * 8);
            cp_commit();
            cp_wait<1>();
        } else {
            cp_wait<0>();
        }
        __syncthreads();

        #pragma unroll
        for (int kk = 0; kk < BK; kk += 16) {
            uint32_t af[2][4];
            #pragma unroll
            for (int mi = 0; mi < 2; mi++) {
                const __nv_bfloat16* ab = &As[buf][warpM * 32 + mi * 16 + qrow][kk + qk];
                af[mi][0] = *(const uint32_t*)ab;
                af[mi][1] = *(const uint32_t*)(ab + 8 * (BK + SKEW));
                af[mi][2] = *(const uint32_t*)(ab + 8);
                af[mi][3] = *(const uint32_t*)(ab + 8 * (BK + SKEW) + 8);
            }
            #pragma unroll
            for (int ni = 0; ni < 8; ni++) {
                const __nv_bfloat16* bb = &Bs[buf][warpN * 64 + ni * 8 + qrow][kk + qk];
                uint32_t b0 = *(const uint32_t*)bb;
                uint32_t b1 = *(const uint32_t*)(bb + 8);
                mma_bf16(acc[0][ni], af[0][0], af[0][1], af[0][2], af[0][3], b0, b1);
                mma_bf16(acc[1][ni], af[1][0], af[1][1], af[1][2], af[1][3], b0, b1);
            }
        }
        __syncthreads();
        buf ^= 1;
    }

    // ---- epilogue: e = 4096*exp(s-10) = 2^(a*C2 + CS), via ex2.approx.f16x2 ----
    const float C2 = 14.4269504089f;    // 10*log2(e)
    const float CS = -2.4269504089f;    // -C2 + 12 (x2^12 scaling keeps f16 normal)
    float colS[8][2];
    #pragma unroll
    for (int ni = 0; ni < 8; ni++) { colS[ni][0] = 0.f; colS[ni][1] = 0.f; }

    #pragma unroll
    for (int mi = 0; mi < 2; mi++) {
        #pragma unroll
        for (int h = 0; h < 2; h++) {
            const int lrow = warpM * 32 + mi * 16 + h * 8 + qrow;
            float rs = 0.f;
            #pragma unroll
            for (int ni = 0; ni < 8; ni++) {
                float x0 = fmaf(acc[mi][ni][h * 2 + 0], C2, CS);
                float x1 = fmaf(acc[mi][ni][h * 2 + 1], C2, CS);
                __half2 he = h2exp2(__floats2half2_rn(x0, x1));
                float2 ef = __half22float2(he);
                if (diag) {
                    const int lcol0 = warpN * 64 + ni * 8 + (lane & 3) * 2;
                    if (lcol0     == lrow) ef.x = 4096.0f;   // exact diagonal: exp(0)*2^12
                    if (lcol0 + 1 == lrow) ef.y = 4096.0f;
                } else {
                    colS[ni][0] += ef.x;
                    colS[ni][1] += ef.y;
                }
                rs += ef.x + ef.y;
            }
            // 4 lanes share a row
            rs += __shfl_xor_sync(0xffffffffu, rs, 1);
            rs += __shfl_xor_sync(0xffffffffu, rs, 2);
            if ((lane & 3) == 0) atomicAdd(&rsmem[lrow], rs);
        }
    }
    if (!diag) {
        #pragma unroll
        for (int ni = 0; ni < 8; ni++) {
            #pragma unroll
            for (int c = 0; c < 2; c++) {
                float v = colS[ni][c];
                v += __shfl_xor_sync(0xffffffffu, v, 4);
                v += __shfl_xor_sync(0xffffffffu, v, 8);
                v += __shfl_xor_sync(0xffffffffu, v, 16);
                if (qrow == 0) {
                    const int lcol = warpN * 64 + ni * 8 + (lane & 3) * 2 + c;
                    atomicAdd(&csmem[lcol], v);
                }
            }
        }
    }

    __syncthreads();
    if (tid < BM) {
        atomicAdd(gsum + rb + tid, rsmem[tid]);
        if (!diag) atomicAdd(gsum + cb + tid, csmem[tid]);
    }
}

// ---------------- per-(b,scale) loss reduction ----------------
__global__ void __launch_bounds__(256)
reduce_kernel()
{
    const int b = blockIdx.x, S = blockIdx.y, tid = threadIdx.x;
    const int N = S ? N1_ : N0_;
    const int H = S ? H1_ : H0_;
    const float* gsum = g_gsum + (S ? B_ * N0_ : 0) + (size_t)b * N;
    const int* cnt = S ? g_cnt1 : g_cnt0;
    const float* posg = g_posg + b * HT_ + (S ? H0_ : 0);

    const float LOGSC = 8.3177661667f;   // ln(4096)
    float local = 0.f;
    for (int n = tid; n < N; n += 256) {
        if (cnt[n] > 0) local += 10.0f + __logf(gsum[n]) - LOGSC;
    }
    for (int k = tid; k < H; k += 256) local -= posg[k];

    #pragma unroll
    for (int o = 16; o > 0; o >>= 1) local += __shfl_down_sync(0xffffffffu, local, o);
    __shared__ float sp[8];
    if ((tid & 31) == 0) sp[tid >> 5] = local;
    __syncthreads();
    if (tid == 0) {
        float t = 0.f;
        #pragma unroll
        for (int i = 0; i < 8; i++) t += sp[i];
        atomicAdd(&g_loss[S], (double)t);
    }
}

// ---------------- finalize ----------------
__global__ void final_kernel(float* out_loss)
{
    double l = 0.0;
    #pragma unroll
    for (int s = 0; s < 2; s++) {
        int nv = g_nvalid[s];
        if (nv > 0) l += g_loss[s] / (double)(B_ * nv);
    }
    *out_loss = (float)l;
}

// ---------------- launch ----------------
extern "C" void kernel_launch(void* const* d_in, const int* in_sizes, int n_in,
                              void* d_out, int out_size)
{
    const float* x0   = (const float*)d_in[0];
    const float* x1   = (const float*)d_in[1];
    const float* w0   = (const float*)d_in[2];
    const float* w1   = (const float*)d_in[3];
    const float* hy0  = (const float*)d_in[4];
    const float* hy1  = (const float*)d_in[5];
    const float* nod0 = (const float*)d_in[6];
    const float* nod1 = (const float*)d_in[7];
    float* out = (float*)d_out;

    float* adj0  = out;
    float* adj1  = out + (size_t)N0_ * H0_;
    float* lossp = out + (size_t)N0_ * H0_ + (size_t)N1_ * H1_;

    __nv_bfloat16 *nx0, *nx1, *nw0, *nw1;
    float *sx0, *sx1, *sw0, *sw1;
    cudaGetSymbolAddress((void**)&nx0, g_nx0);
    cudaGetSymbolAddress((void**)&nx1, g_nx1);
    cudaGetSymbolAddress((void**)&nw0, g_nw0);
    cudaGetSymbolAddress((void**)&nw1, g_nw1);
    cudaGetSymbolAddress((void**)&sx0, g_selfx0);
    cudaGetSymbolAddress((void**)&sx1, g_selfx1);
    cudaGetSymbolAddress((void**)&sw0, g_selfw0);
    cudaGetSymbolAddress((void**)&sw1, g_selfw1);

    init_kernel<<<(GSUMTOT + 255) / 256, 256>>>();

    adj_kernel<0><<<N0_, 128>>>(nod0, hy0, adj0, H0_);
    adj_kernel<1><<<N1_, 128>>>(nod1, hy1, adj1, H1_);
    cnt_kernel<<<2, 256>>>();

    normx_kernel<<<(B_ * L0_) / 8, 256>>>(x0, nx0, sx0, B_ * L0_);
    normx_kernel<<<(B_ * L1_) / 8, 256>>>(x1, nx1, sx1, B_ * L1_);
    normx_kernel<<<WS_ / 8, 256>>>(w0, nw0, sw0, WS_);
    normx_kernel<<<WS_ / 8, 256>>>(w1, nw1, sw1, WS_);

    sim_kernel<<<dim3(P0_ + P1_, B_), 256>>>();
    posg_kernel<<<dim3(HT_, B_), 128>>>();

    reduce_kernel<<<dim3(B_, 2), 256>>>();
    final_kernel<<<1, 1>>>(lossp);
}

// round 6
// speedup vs baseline: 8.8094x; 1.2252x over previous
#include <cuda_runtime.h>
#include <cuda_bf16.h>
#include <cuda_fp16.h>
#include <cstdint>

// ---------------- fixed problem shape ----------------
#define B_   64
#define D_   512
#define L0_  512
#define L1_  256
#define WS_  128
#define H0_  128
#define H1_  64
#define N0_  (L0_ + WS_)   // 640
#define N1_  (L1_ + WS_)   // 384
#define HT_  (H0_ + H1_)   // 192
#define P0_  15            // triangular 128-tile pairs, scale0 (T=5)
#define P1_  6             // scale1 (T=3)

// ---------------- device scratch ----------------
__device__ __nv_bfloat16 g_nx0[(size_t)B_ * L0_ * D_];
__device__ __nv_bfloat16 g_nx1[(size_t)B_ * L1_ * D_];
__device__ __nv_bfloat16 g_nw0[WS_ * D_];
__device__ __nv_bfloat16 g_nw1[WS_ * D_];
__device__ float g_selfx0[B_ * L0_];
__device__ float g_selfx1[B_ * L1_];
__device__ float g_selfw0[WS_];
__device__ float g_selfw1[WS_];
__device__ int   g_eidx0[N0_], g_eidx1[N1_];
__device__ int   g_memb0[N0_], g_memb1[N1_];
__device__ int   g_gstart0[H0_ + 1], g_gstart1[H1_ + 1];
__device__ int   g_cnt0[N0_], g_cnt1[N1_];
__device__ int   g_nvalid[2];
__device__ float g_posg[B_ * HT_];
#define GSUMTOT (B_ * (N0_ + N1_))
__device__ float g_gsum[GSUMTOT];
__device__ double g_loss[2];

// ---------------- init (graph replays -> re-zero every launch) ----------------
__global__ void init_kernel() {
    int i = blockIdx.x * blockDim.x + threadIdx.x;
    if (i < GSUMTOT) g_gsum[i] = 0.f;
    if (i == 0) { g_loss[0] = 0.0; g_loss[1] = 0.0; }
}

// ---------------- adjacency: 4 nodes per block, both scales in one grid ----------------
// softmax row sums to 1 => at most one entry > 0.5 and it is the row max =>
// always inside top-k: adj_bin = (p > 0.5). No top-k machinery needed.
__global__ void __launch_bounds__(128)
adjq_kernel(const float* __restrict__ nod0, const float* __restrict__ hy0,
            const float* __restrict__ nod1, const float* __restrict__ hy1,
            float* __restrict__ adj0, float* __restrict__ adj1)
{
    const int blk = blockIdx.x;
    const int S = (blk >= N0_ / 4);
    const int nbase = (S ? (blk - N0_ / 4) : blk) * 4;
    const int H = S ? H1_ : H0_;
    const float* enod = S ? nod1 : nod0;
    const float* ehy  = S ? hy1  : hy0;
    float* adj_out = S ? adj1 : adj0;
    int* eidx = S ? g_eidx1 : g_eidx0;
    const int tid = threadIdx.x;

    __shared__ float xrow[4][D_];
    __shared__ float et[128][36];
    __shared__ float rbuf[128];
    __shared__ int   widx[4];

    #pragma unroll
    for (int r = 0; r < 4; r++)
        *(float4*)&xrow[r][tid * 4] = *(const float4*)(enod + (size_t)(nbase + r) * D_ + tid * 4);

    float acc[4] = {0.f, 0.f, 0.f, 0.f};
    const int nf4 = H * 8;
    for (int kk = 0; kk < D_; kk += 32) {
        __syncthreads();
        for (int f = tid; f < nf4; f += 128) {
            int h = f >> 3, c4 = f & 7;
            *(float4*)&et[h][c4 * 4] = *(const float4*)(ehy + (size_t)h * D_ + kk + c4 * 4);
        }
        __syncthreads();
        if (tid < H) {
            #pragma unroll
            for (int c4 = 0; c4 < 8; c4++) {
                float4 e4 = *(const float4*)&et[tid][c4 * 4];
                #pragma unroll
                for (int r = 0; r < 4; r++) {
                    float4 x4 = *(const float4*)&xrow[r][kk + c4 * 4];
                    acc[r] = fmaf(x4.x, e4.x, acc[r]);
                    acc[r] = fmaf(x4.y, e4.y, acc[r]);
                    acc[r] = fmaf(x4.z, e4.z, acc[r]);
                    acc[r] = fmaf(x4.w, e4.w, acc[r]);
                }
            }
        }
    }

    #pragma unroll
    for (int r = 0; r < 4; r++) {
        float z = (tid < H) ? fmaxf(3.0f * acc[r], 0.0f) : -1e30f;
        __syncthreads();
        rbuf[tid] = z; __syncthreads();
        for (int o = 64; o > 0; o >>= 1) { if (tid < o) rbuf[tid] = fmaxf(rbuf[tid], rbuf[tid + o]); __syncthreads(); }
        float zmax = rbuf[0]; __syncthreads();
        float e = (tid < H) ? __expf(z - zmax) : 0.f;
        rbuf[tid] = e; __syncthreads();
        for (int o = 64; o > 0; o >>= 1) { if (tid < o) rbuf[tid] += rbuf[tid + o]; __syncthreads(); }
        float ssum = rbuf[0];
        if (tid == 0) widx[r] = -1;
        __syncthreads();
        if (tid < H) {
            int bin = (e / ssum) > 0.5f;
            adj_out[(size_t)(nbase + r) * H + tid] = (float)bin;
            if (bin) widx[r] = tid;
        }
    }
    __syncthreads();
    if (tid < 4) eidx[nbase + tid] = widx[tid];
}

// ---------------- counts + group member lists ----------------
__global__ void __launch_bounds__(256)
cnt_kernel()
{
    const int S = blockIdx.x;
    const int N = S ? N1_ : N0_;
    const int H = S ? H1_ : H0_;
    const int* eidx = S ? g_eidx1 : g_eidx0;
    int* memb = S ? g_memb1 : g_memb0;
    int* gst  = S ? g_gstart1 : g_gstart0;
    int* cnt  = S ? g_cnt1 : g_cnt0;

    __shared__ int sz[128];
    __shared__ int scanb[128];
    __shared__ int cur[128];
    __shared__ int vc;
    const int tid = threadIdx.x;
    if (tid < H) sz[tid] = 0;
    if (tid == 0) vc = 0;
    __syncthreads();
    for (int n = tid; n < N; n += 256) {
        int e = eidx[n];
        if (e >= 0) atomicAdd(&sz[e], 1);
    }
    __syncthreads();
    if (tid < H) scanb[tid] = sz[tid];
    __syncthreads();
    for (int o = 1; o < H; o <<= 1) {
        int v = (tid < H && tid >= o) ? scanb[tid - o] : 0;
        __syncthreads();
        if (tid < H) scanb[tid] += v;
        __syncthreads();
    }
    if (tid < H) { gst[tid] = scanb[tid] - sz[tid]; cur[tid] = scanb[tid] - sz[tid]; }
    if (tid == 0) gst[H] = scanb[H - 1];
    __syncthreads();
    int local = 0;
    for (int n = tid; n < N; n += 256) {
        int e = eidx[n];
        int c = 0;
        if (e >= 0) {
            int p = atomicAdd(&cur[e], 1);
            memb[p] = n;
            c = sz[e] - 1;
        }
        cnt[n] = c;
        if (c > 0) local++;
    }
    atomicAdd(&vc, local);
    __syncthreads();
    if (tid == 0) g_nvalid[S] = vc;
}

// ---------------- normalize -> bf16 + self-dot (warp-per-row, all tensors merged) ----------------
__global__ void __launch_bounds__(256)
normx_kernel(const float* __restrict__ x0, const float* __restrict__ x1,
             const float* __restrict__ w0, const float* __restrict__ w1)
{
    const int gw   = (blockIdx.x * 256 + threadIdx.x) >> 5;
    const int lane = threadIdx.x & 31;
    const float* src;
    __nv_bfloat16* dst;
    float* selfp;
    int r = gw;
    if (r < B_ * L0_)                    { src = x0 + (size_t)r * D_; dst = g_nx0 + (size_t)r * D_; selfp = g_selfx0 + r; }
    else if ((r -= B_ * L0_) < B_ * L1_) { src = x1 + (size_t)r * D_; dst = g_nx1 + (size_t)r * D_; selfp = g_selfx1 + r; }
    else if ((r -= B_ * L1_) < WS_)      { src = w0 + (size_t)r * D_; dst = g_nw0 + (size_t)r * D_; selfp = g_selfw0 + r; }
    else { r -= WS_;                       src = w1 + (size_t)r * D_; dst = g_nw1 + (size_t)r * D_; selfp = g_selfw1 + r; }

    float4 v[4];
    #pragma unroll
    for (int i = 0; i < 4; i++) v[i] = *(const float4*)(src + i * 128 + lane * 4);
    float ss = 0.f;
    #pragma unroll
    for (int i = 0; i < 4; i++) ss += v[i].x*v[i].x + v[i].y*v[i].y + v[i].z*v[i].z + v[i].w*v[i].w;
    #pragma unroll
    for (int o = 16; o > 0; o >>= 1) ss += __shfl_xor_sync(0xffffffffu, ss, o);
    float iv = 1.0f / fmaxf(sqrtf(ss), 1e-12f);
    float sd = 0.f;
    #pragma unroll
    for (int i = 0; i < 4; i++) {
        __nv_bfloat162 p0 = __floats2bfloat162_rn(v[i].x * iv, v[i].y * iv);
        __nv_bfloat162 p1 = __floats2bfloat162_rn(v[i].z * iv, v[i].w * iv);
        float2 f0 = __bfloat1622float2(p0);
        float2 f1 = __bfloat1622float2(p1);
        sd += f0.x*f0.x + f0.y*f0.y + f1.x*f1.x + f1.y*f1.y;
        uint2 pk; pk.x = *(uint32_t*)&p0; pk.y = *(uint32_t*)&p1;
        *(uint2*)(dst + i * 128 + lane * 4) = pk;
    }
    #pragma unroll
    for (int o = 16; o > 0; o >>= 1) sd += __shfl_xor_sync(0xffffffffu, sd, o);
    if (lane == 0) *selfp = sd;
}

// ---------------- per-(b,edge) positive group sums ----------------
// sum_{n!=m in group} s_nm = 10*(||sum of rows||^2 - sum selfdot); cnt within a
// group is sz-1 for all members, so loss needs only this total / (sz-1).
__global__ void __launch_bounds__(128)
posg_kernel()
{
    const int kg = blockIdx.x;
    const int S  = (kg >= H0_);
    const int k  = S ? kg - H0_ : kg;
    const int b  = blockIdx.y;
    const int tid = threadIdx.x;

    const int* gst  = S ? g_gstart1 : g_gstart0;
    const int* memb = S ? g_memb1 : g_memb0;
    const int L = S ? L1_ : L0_;
    const __nv_bfloat16* nx = S ? g_nx1 : g_nx0;
    const __nv_bfloat16* nw = S ? g_nw1 : g_nw0;
    const float* selfx = S ? g_selfx1 : g_selfx0;
    const float* selfw = S ? g_selfw1 : g_selfw0;

    const int s0 = gst[k], s1 = gst[k + 1];
    const int szk = s1 - s0;
    float* outp = &g_posg[b * HT_ + kg];
    if (szk < 2) { if (tid == 0) *outp = 0.f; return; }

    float g0 = 0.f, g1 = 0.f, g2 = 0.f, g3 = 0.f;
    float selfs = 0.f;
    for (int i = s0; i < s1; i++) {
        int n = memb[i];
        const __nv_bfloat16* row = (n < L) ? nx + ((size_t)b * L + n) * D_
                                           : nw + (size_t)(n - L) * D_;
        uint2 u = *(const uint2*)(row + tid * 4);
        __nv_bfloat162 p0 = *(__nv_bfloat162*)&u.x;
        __nv_bfloat162 p1 = *(__nv_bfloat162*)&u.y;
        float2 f0 = __bfloat1622float2(p0);
        float2 f1 = __bfloat1622float2(p1);
        g0 += f0.x; g1 += f0.y; g2 += f1.x; g3 += f1.y;
    }
    for (int i = s0 + tid; i < s1; i += 128) {
        int n = memb[i];
        selfs += (n < L) ? selfx[(size_t)b * L + n] : selfw[n - L];
    }
    float val = g0*g0 + g1*g1 + g2*g2 + g3*g3;
    #pragma unroll
    for (int o = 16; o > 0; o >>= 1) {
        val   += __shfl_xor_sync(0xffffffffu, val, o);
        selfs += __shfl_xor_sync(0xffffffffu, selfs, o);
    }
    __shared__ float sv[4], sf[4];
    if ((tid & 31) == 0) { sv[tid >> 5] = val; sf[tid >> 5] = selfs; }
    __syncthreads();
    if (tid == 0) {
        float gv = sv[0] + sv[1] + sv[2] + sv[3];
        float sc = sf[0] + sf[1] + sf[2] + sf[3];
        *outp = 10.0f * (gv - sc) / (float)(szk - 1);
    }
}

// ---------------- fused sim GEMM (bf16 mma + ldmatrix) + f16x2-exp epilogue ----------------
#define BM 128
#define BN 128
#define BK 32
#define SKEW 8
#define SROW ((BK + SKEW) * 2)      // 80 bytes per smem row
#define TILEB (BM * SROW)           // 10240 bytes per tile buffer
#define NKT (D_ / BK)               // 16

__device__ __forceinline__ uint32_t smem_u32(const void* p) {
    uint32_t a;
    asm("{ .reg .u64 t; cvta.to.shared.u64 t, %1; cvt.u32.u64 %0, t; }" : "=r"(a) : "l"(p));
    return a;
}
__device__ __forceinline__ void cp_async16(uint32_t saddr, const void* gptr) {
    asm volatile("cp.async.cg.shared.global [%0], [%1], 16;\n" :: "r"(saddr), "l"(gptr));
}
__device__ __forceinline__ void cp_commit() { asm volatile("cp.async.commit_group;\n"); }
template<int NN> __device__ __forceinline__ void cp_wait() {
    asm volatile("cp.async.wait_group %0;\n" :: "n"(NN));
}
__device__ __forceinline__ void ldsm_x4(uint32_t r[4], uint32_t saddr) {
    asm volatile("ldmatrix.sync.aligned.m8n8.x4.shared.b16 {%0,%1,%2,%3}, [%4];"
        : "=r"(r[0]), "=r"(r[1]), "=r"(r[2]), "=r"(r[3]) : "r"(saddr));
}
__device__ __forceinline__ void mma_bf16(float c[4],
    uint32_t a0, uint32_t a1, uint32_t a2, uint32_t a3, uint32_t b0, uint32_t b1)
{
    asm volatile("mma.sync.aligned.m16n8k16.row.col.f32.bf16.bf16.f32 "
        "{%0,%1,%2,%3}, {%4,%5,%6,%7}, {%8,%9}, {%0,%1,%2,%3};\n"
        : "+f"(c[0]), "+f"(c[1]), "+f"(c[2]), "+f"(c[3])
        : "r"(a0), "r"(a1), "r"(a2), "r"(a3), "r"(b0), "r"(b1));
}

// one CTA = one (rt,ct) tile pair, ct >= rt; both scales merged in one launch.
__global__ void __launch_bounds__(256, 2)
sim_kernel()
{
    __shared__ __nv_bfloat16 As[2][BM][BK + SKEW];
    __shared__ __nv_bfloat16 Bs[2][BN][BK + SKEW];
    __shared__ float rsmem[BM], csmem[BN];

    const int tid  = threadIdx.x;
    const int lane = tid & 31;
    const int warp = tid >> 5;
    const int warpM = warp >> 1;           // 0..3: 32-row slab
    const int warpN = warp & 1;            // 0..1: 64-col slab

    // decode scale + triangular pair
    int bx = blockIdx.x;
    const int S = (bx >= P0_);
    int p = S ? bx - P0_ : bx;
    const int T = S ? (N1_ >> 7) : (N0_ >> 7);
    int rt = 0;
    while (p >= T - rt) { p -= T - rt; rt++; }
    const int ct = rt + p;
    const bool diag = (rt == ct);

    const int rb = rt * BM, cb = ct * BN;
    const int b  = blockIdx.y;
    const int L = S ? L1_ : L0_;
    const int N = S ? N1_ : N0_;
    const __nv_bfloat16* nx = S ? g_nx1 : g_nx0;
    const __nv_bfloat16* nw = S ? g_nw1 : g_nw0;
    float* gsum = g_gsum + (S ? B_ * N0_ : 0) + (size_t)b * N;

    const __nv_bfloat16* baseA = (rb < L) ? nx + ((size_t)b * L + rb) * D_
                                          : nw + (size_t)(rb - L) * D_;
    const __nv_bfloat16* baseB = (cb < L) ? nx + ((size_t)b * L + cb) * D_
                                          : nw + (size_t)(cb - L) * D_;

    if (tid < BM) { rsmem[tid] = 0.f; csmem[tid] = 0.f; }

    // cp.async slots: 2 x 16B per tile per thread
    const int r0 = tid >> 2, seg0 = tid & 3;
    const int r1 = (tid + 256) >> 2, seg1 = (tid + 256) & 3;
    const uint32_t asb = smem_u32(&As[0][0][0]);
    const uint32_t bsb = smem_u32(&Bs[0][0][0]);
    const uint32_t sA0 = asb + r0 * SROW + seg0 * 16;
    const uint32_t sA1 = asb + r1 * SROW + seg1 * 16;
    const uint32_t sB0 = bsb + r0 * SROW + seg0 * 16;
    const uint32_t sB1 = bsb + r1 * SROW + seg1 * 16;

    // ldmatrix addresses (per-buffer offset added in loop):
    // A: row = warpM*32 + mi*16 + (lane&15); colHalf = (lane>>4)*8
    // B fragments: n = warpN*64 + pr*16 + (lane&7) + ((lane>>4)&1)*8; kHalf = ((lane>>3)&1)*8
    uint32_t aAddr[2], bAddr[4];
    {
        const int arow = (lane & 15), ach = (lane >> 4) * 8;
        #pragma unroll
        for (int mi = 0; mi < 2; mi++)
            aAddr[mi] = asb + (warpM * 32 + mi * 16 + arow) * SROW + ach * 2;
        const int bn = (lane & 7) + ((lane >> 4) & 1) * 8;
        const int bkh = ((lane >> 3) & 1) * 8;
        #pragma unroll
        for (int pr = 0; pr < 4; pr++)
            bAddr[pr] = bsb + (warpN * 64 + pr * 16 + bn) * SROW + bkh * 2;
    }

    float acc[2][8][4];
    #pragma unroll
    for (int mi = 0; mi < 2; mi++)
        #pragma unroll
        for (int ni = 0; ni < 8; ni++)
            #pragma unroll
            for (int r = 0; r < 4; r++) acc[mi][ni][r] = 0.f;

    cp_async16(sA0, baseA + (size_t)r0 * D_ + seg0 * 8);
    cp_async16(sB0, baseB + (size_t)r0 * D_ + seg0 * 8);
    cp_async16(sA1, baseA + (size_t)r1 * D_ + seg1 * 8);
    cp_async16(sB1, baseB + (size_t)r1 * D_ + seg1 * 8);
    cp_commit();

    int buf = 0;
    for (int kt = 0; kt < NKT; ++kt) {
        if (kt + 1 < NKT) {
            const int kb = (kt + 1) * BK;
            const uint32_t bo = (buf ^ 1) * (uint32_t)TILEB;
            cp_async16(sA0 + bo, baseA + (size_t)r0 * D_ + kb + seg0 * 8);
            cp_async16(sB0 + bo, baseB + (size_t)r0 * D_ + kb + seg0 * 8);
            cp_async16(sA1 + bo, baseA + (size_t)r1 * D_ + kb + seg1 * 8);
            cp_async16(sB1 + bo, baseB + (size_t)r1 * D_ + kb + seg1 * 8);
            cp_commit();
            cp_wait<1>();
        } else {
            cp_wait<0>();
        }
        __syncthreads();

        const uint32_t bofs = buf * (uint32_t)TILEB;
        #pragma unroll
        for (int kk = 0; kk < BK; kk += 16) {
            uint32_t af[2][4];
            ldsm_x4(af[0], aAddr[0] + bofs + kk * 2);
            ldsm_x4(af[1], aAddr[1] + bofs + kk * 2);
            #pragma unroll
            for (int pr = 0; pr < 4; pr++) {
                uint32_t bf[4];
                ldsm_x4(bf, bAddr[pr] + bofs + kk * 2);
                mma_bf16(acc[0][pr * 2    ], af[0][0], af[0][1], af[0][2], af[0][3], bf[0], bf[1]);
                mma_bf16(acc[1][pr * 2    ], af[1][0], af[1][1], af[1][2], af[1][3], bf[0], bf[1]);
                mma_bf16(acc[0][pr * 2 + 1], af[0][0], af[0][1], af[0][2], af[0][3], bf[2], bf[3]);
                mma_bf16(acc[1][pr * 2 + 1], af[1][0], af[1][1], af[1][2], af[1][3], bf[2], bf[3]);
            }
        }
        __syncthreads();
        buf ^= 1;
    }

    // ---- epilogue: e = 4096*exp(s-10) = 2^(a*C2 + CS) via ex2.approx.f16x2 ----
    const float C2 = 14.4269504089f;    // 10*log2(e)
    const float CS = -2.4269504089f;    // -C2 + 12 (x2^12 keeps f16 normal)
    const int qrow = lane >> 2;
    float colS[8][2];
    #pragma unroll
    for (int ni = 0; ni < 8; ni++) { colS[ni][0] = 0.f; colS[ni][1] = 0.f; }

    #pragma unroll
    for (int mi = 0; mi < 2; mi++) {
        #pragma unroll
        for (int h = 0; h < 2; h++) {
            const int lrow = warpM * 32 + mi * 16 + h * 8 + qrow;
            float rs = 0.f;
            #pragma unroll
            for (int ni = 0; ni < 8; ni++) {
                float x0 = fmaf(acc[mi][ni][h * 2 + 0], C2, CS);
                float x1 = fmaf(acc[mi][ni][h * 2 + 1], C2, CS);
                __half2 he = h2exp2(__floats2half2_rn(x0, x1));
                float2 ef = __half22float2(he);
                if (diag) {
                    const int lcol0 = warpN * 64 + ni * 8 + (lane & 3) * 2;
                    if (lcol0     == lrow) ef.x = 4096.0f;   // exact diagonal exp(0)*2^12
                    if (lcol0 + 1 == lrow) ef.y = 4096.0f;
                } else {
                    colS[ni][0] += ef.x;
                    colS[ni][1] += ef.y;
                }
                rs += ef.x + ef.y;
            }
            rs += __shfl_xor_sync(0xffffffffu, rs, 1);
            rs += __shfl_xor_sync(0xffffffffu, rs, 2);
            if ((lane & 3) == 0) atomicAdd(&rsmem[lrow], rs);
        }
    }
    if (!diag) {
        #pragma unroll
        for (int ni = 0; ni < 8; ni++) {
            #pragma unroll
            for (int c = 0; c < 2; c++) {
                float v = colS[ni][c];
                v += __shfl_xor_sync(0xffffffffu, v, 4);
                v += __shfl_xor_sync(0xffffffffu, v, 8);
                v += __shfl_xor_sync(0xffffffffu, v, 16);
                if (qrow == 0 && (lane & 3) * 2 + c < 8) {   // one writer per col
                    const int lcol = warpN * 64 + ni * 8 + (lane & 3) * 2 + c;
                    atomicAdd(&csmem[lcol], v);
                }
            }
        }
    }

    __syncthreads();
    if (tid < BM) {
        atomicAdd(gsum + rb + tid, rsmem[tid]);
        if (!diag) atomicAdd(gsum + cb + tid, csmem[tid]);
    }
}

// ---------------- per-(b,scale) loss reduction ----------------
__global__ void __launch_bounds__(256)
reduce_kernel()
{
    const int b = blockIdx.x, S = blockIdx.y, tid = threadIdx.x;
    const int N = S ? N1_ : N0_;
    const int H = S ? H1_ : H0_;
    const float* gsum = g_gsum + (S ? B_ * N0_ : 0) + (size_t)b * N;
    const int* cnt = S ? g_cnt1 : g_cnt0;
    const float* posg = g_posg + b * HT_ + (S ? H0_ : 0);

    const float LOGSC = 8.3177661667f;   // ln(4096)
    float local = 0.f;
    for (int n = tid; n < N; n += 256) {
        if (cnt[n] > 0) local += 10.0f + __logf(gsum[n]) - LOGSC;
    }
    for (int k = tid; k < H; k += 256) local -= posg[k];

    #pragma unroll
    for (int o = 16; o > 0; o >>= 1) local += __shfl_down_sync(0xffffffffu, local, o);
    __shared__ float sp[8];
    if ((tid & 31) == 0) sp[tid >> 5] = local;
    __syncthreads();
    if (tid == 0) {
        float t = 0.f;
        #pragma unroll
        for (int i = 0; i < 8; i++) t += sp[i];
        atomicAdd(&g_loss[S], (double)t);
    }
}

// ---------------- finalize ----------------
__global__ void final_kernel(float* out_loss)
{
    double l = 0.0;
    #pragma unroll
    for (int s = 0; s < 2; s++) {
        int nv = g_nvalid[s];
        if (nv > 0) l += g_loss[s] / (double)(B_ * nv);
    }
    *out_loss = (float)l;
}

// ---------------- launch ----------------
extern "C" void kernel_launch(void* const* d_in, const int* in_sizes, int n_in,
                              void* d_out, int out_size)
{
    const float* x0   = (const float*)d_in[0];
    const float* x1   = (const float*)d_in[1];
    const float* w0   = (const float*)d_in[2];
    const float* w1   = (const float*)d_in[3];
    const float* hy0  = (const float*)d_in[4];
    const float* hy1  = (const float*)d_in[5];
    const float* nod0 = (const float*)d_in[6];
    const float* nod1 = (const float*)d_in[7];
    float* out = (float*)d_out;

    float* adj0  = out;
    float* adj1  = out + (size_t)N0_ * H0_;
    float* lossp = out + (size_t)N0_ * H0_ + (size_t)N1_ * H1_;

    init_kernel<<<(GSUMTOT + 255) / 256, 256>>>();

    adjq_kernel<<<N0_ / 4 + N1_ / 4, 128>>>(nod0, hy0, nod1, hy1, adj0, adj1);
    cnt_kernel<<<2, 256>>>();

    const int nrows = B_ * L0_ + B_ * L1_ + 2 * WS_;   // 49408
    normx_kernel<<<nrows / 8, 256>>>(x0, x1, w0, w1);

    sim_kernel<<<dim3(P0_ + P1_, B_), 256>>>();
    posg_kernel<<<dim3(HT_, B_), 128>>>();

    reduce_kernel<<<dim3(B_, 2), 256>>>();
    final_kernel<<<1, 1>>>(lossp);
}

// round 7
// speedup vs baseline: 9.1969x; 1.0440x over previous
#include <cuda_runtime.h>
#include <cuda_bf16.h>
#include <cuda_fp16.h>
#include <cstdint>

// ---------------- fixed problem shape ----------------
#define B_   64
#define D_   512
#define L0_  512
#define L1_  256
#define WS_  128
#define H0_  128
#define H1_  64
#define N0_  (L0_ + WS_)   // 640
#define N1_  (L1_ + WS_)   // 384
#define HT_  (H0_ + H1_)   // 192
#define P0_  15            // triangular 128-tile pairs, scale0 (T=5)
#define P1_  6             // scale1 (T=3)

// ---------------- device scratch ----------------
__device__ __nv_bfloat16 g_nx0[(size_t)B_ * L0_ * D_];
__device__ __nv_bfloat16 g_nx1[(size_t)B_ * L1_ * D_];
__device__ __nv_bfloat16 g_nw0[WS_ * D_];
__device__ __nv_bfloat16 g_nw1[WS_ * D_];
__device__ float g_selfx0[B_ * L0_];
__device__ float g_selfx1[B_ * L1_];
__device__ float g_selfw0[WS_];
__device__ float g_selfw1[WS_];
__device__ int   g_eidx0[N0_], g_eidx1[N1_];
__device__ int   g_memb0[N0_], g_memb1[N1_];
__device__ int   g_gstart0[H0_ + 1], g_gstart1[H1_ + 1];
__device__ int   g_cnt0[N0_], g_cnt1[N1_];
__device__ int   g_nvalid[2];
__device__ float g_posg[B_ * HT_];
#define GSUMTOT (B_ * (N0_ + N1_))   // 65536
__device__ float g_gsum[GSUMTOT];
__device__ float g_wwsum[2][WS_];    // batch-invariant word-word tile row sums
__device__ double g_loss[2];

// ---------------- adjacency (+ fused accumulator init): 4 nodes/block ----------------
// softmax row sums to 1 => at most one entry > 0.5 and it is the row max =>
// always inside top-k: adj_bin = (p > 0.5). No top-k machinery needed.
__global__ void __launch_bounds__(128)
adjq_kernel(const float* __restrict__ nod0, const float* __restrict__ hy0,
            const float* __restrict__ nod1, const float* __restrict__ hy1,
            float* __restrict__ adj0, float* __restrict__ adj1)
{
    const int blk = blockIdx.x;
    const int tid = threadIdx.x;

    // fused init: zero g_gsum / g_loss (graph replays re-run this every launch)
    {
        int gid = blk * 128 + tid;              // 0..32767
        g_gsum[gid] = 0.f;
        g_gsum[gid + 32768] = 0.f;
        if (gid == 0) { g_loss[0] = 0.0; g_loss[1] = 0.0; }
    }

    const int S = (blk >= N0_ / 4);
    const int nbase = (S ? (blk - N0_ / 4) : blk) * 4;
    const int H = S ? H1_ : H0_;
    const float* enod = S ? nod1 : nod0;
    const float* ehy  = S ? hy1  : hy0;
    float* adj_out = S ? adj1 : adj0;
    int* eidx = S ? g_eidx1 : g_eidx0;

    __shared__ float xrow[4][D_];
    __shared__ float et[128][36];
    __shared__ float rbuf[128];
    __shared__ int   widx[4];

    #pragma unroll
    for (int r = 0; r < 4; r++)
        *(float4*)&xrow[r][tid * 4] = *(const float4*)(enod + (size_t)(nbase + r) * D_ + tid * 4);

    float acc[4] = {0.f, 0.f, 0.f, 0.f};
    const int nf4 = H * 8;
    for (int kk = 0; kk < D_; kk += 32) {
        __syncthreads();
        for (int f = tid; f < nf4; f += 128) {
            int h = f >> 3, c4 = f & 7;
            *(float4*)&et[h][c4 * 4] = *(const float4*)(ehy + (size_t)h * D_ + kk + c4 * 4);
        }
        __syncthreads();
        if (tid < H) {
            #pragma unroll
            for (int c4 = 0; c4 < 8; c4++) {
                float4 e4 = *(const float4*)&et[tid][c4 * 4];
                #pragma unroll
                for (int r = 0; r < 4; r++) {
                    float4 x4 = *(const float4*)&xrow[r][kk + c4 * 4];
                    acc[r] = fmaf(x4.x, e4.x, acc[r]);
                    acc[r] = fmaf(x4.y, e4.y, acc[r]);
                    acc[r] = fmaf(x4.z, e4.z, acc[r]);
                    acc[r] = fmaf(x4.w, e4.w, acc[r]);
                }
            }
        }
    }

    #pragma unroll
    for (int r = 0; r < 4; r++) {
        float z = (tid < H) ? fmaxf(3.0f * acc[r], 0.0f) : -1e30f;
        __syncthreads();
        rbuf[tid] = z; __syncthreads();
        for (int o = 64; o > 0; o >>= 1) { if (tid < o) rbuf[tid] = fmaxf(rbuf[tid], rbuf[tid + o]); __syncthreads(); }
        float zmax = rbuf[0]; __syncthreads();
        float e = (tid < H) ? __expf(z - zmax) : 0.f;
        rbuf[tid] = e; __syncthreads();
        for (int o = 64; o > 0; o >>= 1) { if (tid < o) rbuf[tid] += rbuf[tid + o]; __syncthreads(); }
        float ssum = rbuf[0];
        if (tid == 0) widx[r] = -1;
        __syncthreads();
        if (tid < H) {
            int bin = (e / ssum) > 0.5f;
            adj_out[(size_t)(nbase + r) * H + tid] = (float)bin;
            if (bin) widx[r] = tid;
        }
    }
    __syncthreads();
    if (tid < 4) eidx[nbase + tid] = widx[tid];
}

// ---------------- counts + group member lists ----------------
__global__ void __launch_bounds__(256)
cnt_kernel()
{
    const int S = blockIdx.x;
    const int N = S ? N1_ : N0_;
    const int H = S ? H1_ : H0_;
    const int* eidx = S ? g_eidx1 : g_eidx0;
    int* memb = S ? g_memb1 : g_memb0;
    int* gst  = S ? g_gstart1 : g_gstart0;
    int* cnt  = S ? g_cnt1 : g_cnt0;

    __shared__ int sz[128];
    __shared__ int scanb[128];
    __shared__ int cur[128];
    __shared__ int vc;
    const int tid = threadIdx.x;
    if (tid < H) sz[tid] = 0;
    if (tid == 0) vc = 0;
    __syncthreads();
    for (int n = tid; n < N; n += 256) {
        int e = eidx[n];
        if (e >= 0) atomicAdd(&sz[e], 1);
    }
    __syncthreads();
    if (tid < H) scanb[tid] = sz[tid];
    __syncthreads();
    for (int o = 1; o < H; o <<= 1) {
        int v = (tid < H && tid >= o) ? scanb[tid - o] : 0;
        __syncthreads();
        if (tid < H) scanb[tid] += v;
        __syncthreads();
    }
    if (tid < H) { gst[tid] = scanb[tid] - sz[tid]; cur[tid] = scanb[tid] - sz[tid]; }
    if (tid == 0) gst[H] = scanb[H - 1];
    __syncthreads();
    int local = 0;
    for (int n = tid; n < N; n += 256) {
        int e = eidx[n];
        int c = 0;
        if (e >= 0) {
            int p = atomicAdd(&cur[e], 1);
            memb[p] = n;
            c = sz[e] - 1;
        }
        cnt[n] = c;
        if (c > 0) local++;
    }
    atomicAdd(&vc, local);
    __syncthreads();
    if (tid == 0) g_nvalid[S] = vc;
}

// ---------------- normalize -> bf16 + self-dot (warp-per-row, all tensors merged) ----------------
__global__ void __launch_bounds__(256)
normx_kernel(const float* __restrict__ x0, const float* __restrict__ x1,
             const float* __restrict__ w0, const float* __restrict__ w1)
{
    const int gw   = (blockIdx.x * 256 + threadIdx.x) >> 5;
    const int lane = threadIdx.x & 31;
    const float* src;
    __nv_bfloat16* dst;
    float* selfp;
    int r = gw;
    if (r < B_ * L0_)                    { src = x0 + (size_t)r * D_; dst = g_nx0 + (size_t)r * D_; selfp = g_selfx0 + r; }
    else if ((r -= B_ * L0_) < B_ * L1_) { src = x1 + (size_t)r * D_; dst = g_nx1 + (size_t)r * D_; selfp = g_selfx1 + r; }
    else if ((r -= B_ * L1_) < WS_)      { src = w0 + (size_t)r * D_; dst = g_nw0 + (size_t)r * D_; selfp = g_selfw0 + r; }
    else { r -= WS_;                       src = w1 + (size_t)r * D_; dst = g_nw1 + (size_t)r * D_; selfp = g_selfw1 + r; }

    float4 v[4];
    #pragma unroll
    for (int i = 0; i < 4; i++) v[i] = *(const float4*)(src + i * 128 + lane * 4);
    float ss = 0.f;
    #pragma unroll
    for (int i = 0; i < 4; i++) ss += v[i].x*v[i].x + v[i].y*v[i].y + v[i].z*v[i].z + v[i].w*v[i].w;
    #pragma unroll
    for (int o = 16; o > 0; o >>= 1) ss += __shfl_xor_sync(0xffffffffu, ss, o);
    float iv = 1.0f / fmaxf(sqrtf(ss), 1e-12f);
    float sd = 0.f;
    #pragma unroll
    for (int i = 0; i < 4; i++) {
        __nv_bfloat162 p0 = __floats2bfloat162_rn(v[i].x * iv, v[i].y * iv);
        __nv_bfloat162 p1 = __floats2bfloat162_rn(v[i].z * iv, v[i].w * iv);
        float2 f0 = __bfloat1622float2(p0);
        float2 f1 = __bfloat1622float2(p1);
        sd += f0.x*f0.x + f0.y*f0.y + f1.x*f1.x + f1.y*f1.y;
        uint2 pk; pk.x = *(uint32_t*)&p0; pk.y = *(uint32_t*)&p1;
        *(uint2*)(dst + i * 128 + lane * 4) = pk;
    }
    #pragma unroll
    for (int o = 16; o > 0; o >>= 1) sd += __shfl_xor_sync(0xffffffffu, sd, o);
    if (lane == 0) *selfp = sd;
}

// ---------------- per-(b,edge) positive group sums ----------------
// sum_{n!=m in group} s_nm = 10*(||sum of rows||^2 - sum selfdot); cnt within a
// group is sz-1 for all members, so loss needs only this total / (sz-1).
__global__ void __launch_bounds__(128)
posg_kernel()
{
    const int kg = blockIdx.x;
    const int S  = (kg >= H0_);
    const int k  = S ? kg - H0_ : kg;
    const int b  = blockIdx.y;
    const int tid = threadIdx.x;

    const int* gst  = S ? g_gstart1 : g_gstart0;
    const int* memb = S ? g_memb1 : g_memb0;
    const int L = S ? L1_ : L0_;
    const __nv_bfloat16* nx = S ? g_nx1 : g_nx0;
    const __nv_bfloat16* nw = S ? g_nw1 : g_nw0;
    const float* selfx = S ? g_selfx1 : g_selfx0;
    const float* selfw = S ? g_selfw1 : g_selfw0;

    const int s0 = gst[k], s1 = gst[k + 1];
    const int szk = s1 - s0;
    float* outp = &g_posg[b * HT_ + kg];
    if (szk < 2) { if (tid == 0) *outp = 0.f; return; }

    float g0 = 0.f, g1 = 0.f, g2 = 0.f, g3 = 0.f;
    float selfs = 0.f;
    for (int i = s0; i < s1; i++) {
        int n = memb[i];
        const __nv_bfloat16* row = (n < L) ? nx + ((size_t)b * L + n) * D_
                                           : nw + (size_t)(n - L) * D_;
        uint2 u = *(const uint2*)(row + tid * 4);
        __nv_bfloat162 p0 = *(__nv_bfloat162*)&u.x;
        __nv_bfloat162 p1 = *(__nv_bfloat162*)&u.y;
        float2 f0 = __bfloat1622float2(p0);
        float2 f1 = __bfloat1622float2(p1);
        g0 += f0.x; g1 += f0.y; g2 += f1.x; g3 += f1.y;
    }
    for (int i = s0 + tid; i < s1; i += 128) {
        int n = memb[i];
        selfs += (n < L) ? selfx[(size_t)b * L + n] : selfw[n - L];
    }
    float val = g0*g0 + g1*g1 + g2*g2 + g3*g3;
    #pragma unroll
    for (int o = 16; o > 0; o >>= 1) {
        val   += __shfl_xor_sync(0xffffffffu, val, o);
        selfs += __shfl_xor_sync(0xffffffffu, selfs, o);
    }
    __shared__ float sv[4], sf[4];
    if ((tid & 31) == 0) { sv[tid >> 5] = val; sf[tid >> 5] = selfs; }
    __syncthreads();
    if (tid == 0) {
        float gv = sv[0] + sv[1] + sv[2] + sv[3];
        float sc = sf[0] + sf[1] + sf[2] + sf[3];
        *outp = 10.0f * (gv - sc) / (float)(szk - 1);
    }
}

// ---------------- fused sim GEMM (bf16 mma + ldmatrix, 3-stage pipeline) ----------------
#define BM 128
#define BN 128
#define BK 32
#define SKEW 8
#define SROW ((BK + SKEW) * 2)      // 80 bytes per smem row
#define TILEB (BM * SROW)           // 10240 bytes per tile buffer
#define NKT (D_ / BK)               // 16
#define NSTAGE 3
#define SIM_DSMEM (2 * NSTAGE * TILEB)   // 61440

__device__ __forceinline__ uint32_t smem_u32(const void* p) {
    uint32_t a;
    asm("{ .reg .u64 t; cvta.to.shared.u64 t, %1; cvt.u32.u64 %0, t; }" : "=r"(a) : "l"(p));
    return a;
}
__device__ __forceinline__ void cp_async16(uint32_t saddr, const void* gptr) {
    asm volatile("cp.async.cg.shared.global [%0], [%1], 16;\n" :: "r"(saddr), "l"(gptr));
}
__device__ __forceinline__ void cp_commit() { asm volatile("cp.async.commit_group;\n"); }
template<int NN> __device__ __forceinline__ void cp_wait() {
    asm volatile("cp.async.wait_group %0;\n" :: "n"(NN));
}
__device__ __forceinline__ void ldsm_x4(uint32_t r[4], uint32_t saddr) {
    asm volatile("ldmatrix.sync.aligned.m8n8.x4.shared.b16 {%0,%1,%2,%3}, [%4];"
        : "=r"(r[0]), "=r"(r[1]), "=r"(r[2]), "=r"(r[3]) : "r"(saddr));
}
__device__ __forceinline__ void mma_bf16(float c[4],
    uint32_t a0, uint32_t a1, uint32_t a2, uint32_t a3, uint32_t b0, uint32_t b1)
{
    asm volatile("mma.sync.aligned.m16n8k16.row.col.f32.bf16.bf16.f32 "
        "{%0,%1,%2,%3}, {%4,%5,%6,%7}, {%8,%9}, {%0,%1,%2,%3};\n"
        : "+f"(c[0]), "+f"(c[1]), "+f"(c[2]), "+f"(c[3])
        : "r"(a0), "r"(a1), "r"(a2), "r"(a3), "r"(b0), "r"(b1));
}

// one CTA = one (rt,ct) tile pair, ct >= rt; both scales merged in one launch.
// word-word diag tiles are batch-invariant: computed only at b==0 into g_wwsum.
__global__ void __launch_bounds__(256, 2)
sim_kernel()
{
    extern __shared__ char dsm[];
    __shared__ float rsmem[BM], csmem[BN];

    const int tid  = threadIdx.x;
    const int lane = tid & 31;
    const int warp = tid >> 5;
    const int warpM = warp >> 1;
    const int warpN = warp & 1;

    // decode scale + triangular pair
    int bx = blockIdx.x;
    const int S = (bx >= P0_);
    int p = S ? bx - P0_ : bx;
    const int T = S ? (N1_ >> 7) : (N0_ >> 7);
    int rt = 0;
    while (p >= T - rt) { p -= T - rt; rt++; }
    const int ct = rt + p;
    const bool diag = (rt == ct);

    const int rb = rt * BM, cb = ct * BN;
    const int b  = blockIdx.y;
    const int L = S ? L1_ : L0_;
    const int N = S ? N1_ : N0_;
    const bool ww = diag && (rb >= L);       // word-word tile: batch-invariant
    if (ww && b != 0) return;

    const __nv_bfloat16* nx = S ? g_nx1 : g_nx0;
    const __nv_bfloat16* nw = S ? g_nw1 : g_nw0;
    float* gsum = g_gsum + (S ? B_ * N0_ : 0) + (size_t)b * N;

    const __nv_bfloat16* baseA = (rb < L) ? nx + ((size_t)b * L + rb) * D_
                                          : nw + (size_t)(rb - L) * D_;
    const __nv_bfloat16* baseB = (cb < L) ? nx + ((size_t)b * L + cb) * D_
                                          : nw + (size_t)(cb - L) * D_;

    if (tid < BM) { rsmem[tid] = 0.f; csmem[tid] = 0.f; }

    // cp.async slots: 2 x 16B per tile per thread
    const int r0 = tid >> 2, seg0 = tid & 3;
    const int r1 = (tid + 256) >> 2, seg1 = (tid + 256) & 3;
    const uint32_t asb = smem_u32(dsm);                       // A stages 0..2
    const uint32_t bsb = asb + NSTAGE * TILEB;                // B stages 0..2
    const uint32_t sA0 = asb + r0 * SROW + seg0 * 16;
    const uint32_t sA1 = asb + r1 * SROW + seg1 * 16;
    const uint32_t sB0 = bsb + r0 * SROW + seg0 * 16;
    const uint32_t sB1 = bsb + r1 * SROW + seg1 * 16;

    // ldmatrix base addresses (stage offset added in loop)
    uint32_t aAddr[2], bAddr[4];
    {
        const int arow = (lane & 15), ach = (lane >> 4) * 8;
        #pragma unroll
        for (int mi = 0; mi < 2; mi++)
            aAddr[mi] = asb + (warpM * 32 + mi * 16 + arow) * SROW + ach * 2;
        const int bn = (lane & 7) + ((lane >> 4) & 1) * 8;
        const int bkh = ((lane >> 3) & 1) * 8;
        #pragma unroll
        for (int pr = 0; pr < 4; pr++)
            bAddr[pr] = bsb + (warpN * 64 + pr * 16 + bn) * SROW + bkh * 2;
    }

    float acc[2][8][4];
    #pragma unroll
    for (int mi = 0; mi < 2; mi++)
        #pragma unroll
        for (int ni = 0; ni < 8; ni++)
            #pragma unroll
            for (int r = 0; r < 4; r++) acc[mi][ni][r] = 0.f;

    auto load_stage = [&](int st, int kt) {
        const uint32_t so = (uint32_t)st * TILEB;
        const int kb = kt * BK;
        cp_async16(sA0 + so, baseA + (size_t)r0 * D_ + kb + seg0 * 8);
        cp_async16(sB0 + so, baseB + (size_t)r0 * D_ + kb + seg0 * 8);
        cp_async16(sA1 + so, baseA + (size_t)r1 * D_ + kb + seg1 * 8);
        cp_async16(sB1 + so, baseB + (size_t)r1 * D_ + kb + seg1 * 8);
        cp_commit();
    };

    load_stage(0, 0);
    load_stage(1, 1);

    int st = 0;
    #pragma unroll 1
    for (int kt = 0; kt < NKT; ++kt) {
        if (kt == NKT - 1) cp_wait<0>(); else cp_wait<1>();
        __syncthreads();   // stage st data visible; stage (st+2)%3 fully drained by all warps
        if (kt + 2 < NKT) {
            int nst = st + 2; if (nst >= NSTAGE) nst -= NSTAGE;
            load_stage(nst, kt + 2);
        }

        const uint32_t bofs = (uint32_t)st * TILEB;
        #pragma unroll
        for (int kk = 0; kk < BK; kk += 16) {
            uint32_t af[2][4];
            ldsm_x4(af[0], aAddr[0] + bofs + kk * 2);
            ldsm_x4(af[1], aAddr[1] + bofs + kk * 2);
            #pragma unroll
            for (int pr = 0; pr < 4; pr++) {
                uint32_t bf[4];
                ldsm_x4(bf, bAddr[pr] + bofs + kk * 2);
                mma_bf16(acc[0][pr * 2    ], af[0][0], af[0][1], af[0][2], af[0][3], bf[0], bf[1]);
                mma_bf16(acc[1][pr * 2    ], af[1][0], af[1][1], af[1][2], af[1][3], bf[0], bf[1]);
                mma_bf16(acc[0][pr * 2 + 1], af[0][0], af[0][1], af[0][2], af[0][3], bf[2], bf[3]);
                mma_bf16(acc[1][pr * 2 + 1], af[1][0], af[1][1], af[1][2], af[1][3], bf[2], bf[3]);
            }
        }
        if (++st >= NSTAGE) st = 0;
    }

    // ---- epilogue: e = 4096*exp(s-10) = 2^(a*C2 + CS) via ex2.approx.f16x2 ----
    const float C2 = 14.4269504089f;    // 10*log2(e)
    const float CS = -2.4269504089f;    // -C2 + 12 (x2^12 keeps f16 normal)
    const int qrow = lane >> 2;
    float colS[8][2];
    #pragma unroll
    for (int ni = 0; ni < 8; ni++) { colS[ni][0] = 0.f; colS[ni][1] = 0.f; }

    #pragma unroll
    for (int mi = 0; mi < 2; mi++) {
        #pragma unroll
        for (int h = 0; h < 2; h++) {
            const int lrow = warpM * 32 + mi * 16 + h * 8 + qrow;
            float rs = 0.f;
            #pragma unroll
            for (int ni = 0; ni < 8; ni++) {
                float x0 = fmaf(acc[mi][ni][h * 2 + 0], C2, CS);
                float x1 = fmaf(acc[mi][ni][h * 2 + 1], C2, CS);
                __half2 he = h2exp2(__floats2half2_rn(x0, x1));
                float2 ef = __half22float2(he);
                if (diag) {
                    const int lcol0 = warpN * 64 + ni * 8 + (lane & 3) * 2;
                    if (lcol0     == lrow) ef.x = 4096.0f;   // exact diagonal exp(0)*2^12
                    if (lcol0 + 1 == lrow) ef.y = 4096.0f;
                } else {
                    colS[ni][0] += ef.x;
                    colS[ni][1] += ef.y;
                }
                rs += ef.x + ef.y;
            }
            rs += __shfl_xor_sync(0xffffffffu, rs, 1);
            rs += __shfl_xor_sync(0xffffffffu, rs, 2);
            if ((lane & 3) == 0) atomicAdd(&rsmem[lrow], rs);
        }
    }
    if (!diag) {
        #pragma unroll
        for (int ni = 0; ni < 8; ni++) {
            #pragma unroll
            for (int c = 0; c < 2; c++) {
                float v = colS[ni][c];
                v += __shfl_xor_sync(0xffffffffu, v, 4);
                v += __shfl_xor_sync(0xffffffffu, v, 8);
                v += __shfl_xor_sync(0xffffffffu, v, 16);
                if (qrow == 0) {
                    const int lcol = warpN * 64 + ni * 8 + (lane & 3) * 2 + c;
                    atomicAdd(&csmem[lcol], v);
                }
            }
        }
    }

    __syncthreads();
    if (tid < BM) {
        if (ww) {
            g_wwsum[S][tid] = rsmem[tid];       // written once (b==0); not accumulated
        } else {
            atomicAdd(gsum + rb + tid, rsmem[tid]);
            if (!diag) atomicAdd(gsum + cb + tid, csmem[tid]);
        }
    }
}

// ---------------- per-(b,scale) loss reduction ----------------
__global__ void __launch_bounds__(256)
reduce_kernel()
{
    const int b = blockIdx.x, S = blockIdx.y, tid = threadIdx.x;
    const int N = S ? N1_ : N0_;
    const int H = S ? H1_ : H0_;
    const int L = S ? L1_ : L0_;
    const float* gsum = g_gsum + (S ? B_ * N0_ : 0) + (size_t)b * N;
    const int* cnt = S ? g_cnt1 : g_cnt0;
    const float* posg = g_posg + b * HT_ + (S ? H0_ : 0);

    const float LOGSC = 8.3177661667f;   // ln(4096)
    float local = 0.f;
    for (int n = tid; n < N; n += 256) {
        if (cnt[n] > 0) {
            float rs = gsum[n];
            if (n >= L) rs += g_wwsum[S][n - L];    // batch-invariant word-word part
            local += 10.0f + __logf(rs) - LOGSC;
        }
    }
    for (int k = tid; k < H; k += 256) local -= posg[k];

    #pragma unroll
    for (int o = 16; o > 0; o >>= 1) local += __shfl_down_sync(0xffffffffu, local, o);
    __shared__ float sp[8];
    if ((tid & 31) == 0) sp[tid >> 5] = local;
    __syncthreads();
    if (tid == 0) {
        float t = 0.f;
        #pragma unroll
        for (int i = 0; i < 8; i++) t += sp[i];
        atomicAdd(&g_loss[S], (double)t);
    }
}

// ---------------- finalize ----------------
__global__ void final_kernel(float* out_loss)
{
    double l = 0.0;
    #pragma unroll
    for (int s = 0; s < 2; s++) {
        int nv = g_nvalid[s];
        if (nv > 0) l += g_loss[s] / (double)(B_ * nv);
    }
    *out_loss = (float)l;
}

// ---------------- launch ----------------
extern "C" void kernel_launch(void* const* d_in, const int* in_sizes, int n_in,
                              void* d_out, int out_size)
{
    const float* x0   = (const float*)d_in[0];
    const float* x1   = (const float*)d_in[1];
    const float* w0   = (const float*)d_in[2];
    const float* w1   = (const float*)d_in[3];
    const float* hy0  = (const float*)d_in[4];
    const float* hy1  = (const float*)d_in[5];
    const float* nod0 = (const float*)d_in[6];
    const float* nod1 = (const float*)d_in[7];
    float* out = (float*)d_out;

    float* adj0  = out;
    float* adj1  = out + (size_t)N0_ * H0_;
    float* lossp = out + (size_t)N0_ * H0_ + (size_t)N1_ * H1_;

    static bool attr_done = false;
    if (!attr_done) {
        cudaFuncSetAttribute(sim_kernel, cudaFuncAttributeMaxDynamicSharedMemorySize, SIM_DSMEM);
        attr_done = true;
    }

    adjq_kernel<<<N0_ / 4 + N1_ / 4, 128>>>(nod0, hy0, nod1, hy1, adj0, adj1);
    cnt_kernel<<<2, 256>>>();

    const int nrows = B_ * L0_ + B_ * L1_ + 2 * WS_;   // 49408
    normx_kernel<<<nrows / 8, 256>>>(x0, x1, w0, w1);

    sim_kernel<<<dim3(P0_ + P1_, B_), 256, SIM_DSMEM>>>();
    posg_kernel<<<dim3(HT_, B_), 128>>>();

    reduce_kernel<<<dim3(B_, 2), 256>>>();
    final_kernel<<<1, 1>>>(lossp);
}